// round 13
// baseline (speedup 1.0000x reference)
#include <cuda_runtime.h>
#include <cuda_bf16.h>
#include <cuda_fp16.h>
#include <math.h>
#include <float.h>
#include <cstdint>

// Problem constants
#define HIDDEN    2048
#define NUM_HEADS 16
#define NUM_KV    8
#define HEAD_DIM  128
#define Q_SIZE    (NUM_HEADS * HEAD_DIM)        // 2048
#define KV_SIZE   (NUM_KV * HEAD_DIM)           // 1024
#define QKV_COLS  (Q_SIZE + 2 * KV_SIZE)        // 4096
#define SCALE     0.08838834764831845f          // 128^-0.5
#define SCALE_L2E 0.12751985675839602f          // SCALE * log2(e)
#define RMS_EPS   1e-6f

#define MAX_T 4096

// Scratch (static device globals)
__device__ float g_qkv[(size_t)MAX_T * QKV_COLS];
__device__ __half g_hid[(size_t)MAX_T * HIDDEN];
__device__ __half g_w1_h[(size_t)QKV_COLS * HIDDEN];
__device__ __half g_w1_l[(size_t)QKV_COLS * HIDDEN];
__device__ __half g_w2_h[(size_t)HIDDEN * Q_SIZE];
__device__ __half g_w2_l[(size_t)HIDDEN * Q_SIZE];
__device__ __half g_at[(size_t)MAX_T * Q_SIZE];
__device__ __half g_q[(size_t)MAX_T * Q_SIZE];              // single fp16 Q
__device__ __half g_k_h[(size_t)NUM_KV * MAX_T * HEAD_DIM];
__device__ __half g_k_l[(size_t)NUM_KV * MAX_T * HEAD_DIM];
__device__ __half g_v[(size_t)NUM_KV * HEAD_DIM * MAX_T];   // [kvh][d][t]

// ===========================================================================
// Helpers
// ===========================================================================
__device__ __forceinline__ uint32_t smem_to_u32(const void* p) {
    uint32_t a;
    asm("{ .reg .u64 t; cvta.to.shared.u64 t, %1; cvt.u32.u64 %0, t; }"
        : "=r"(a) : "l"(p));
    return a;
}
__device__ __forceinline__ void split_h16(float x, __half& h, __half& l) {
    h = __float2half_rn(x);
    l = __float2half_rn(x - __half2float(h));
}
__device__ __forceinline__ float ex2f(float x) {
    float r;
    asm("ex2.approx.f32 %0, %1;" : "=f"(r) : "f"(x));
    return r;
}
__device__ __forceinline__ uint32_t cvt_h2(float a, float b) {
    uint32_t r;
    asm("cvt.rn.f16x2.f32 %0, %1, %2;" : "=r"(r) : "f"(b), "f"(a));
    return r;
}
__device__ __forceinline__ uint32_t pack_h2(__half a, __half b) {
    __half2 t = __halves2half2(a, b);
    return *reinterpret_cast<uint32_t*>(&t);
}

__device__ __forceinline__ void mma_f16(float* d, const uint32_t* a,
                                        uint32_t b0, uint32_t b1) {
    asm volatile(
        "mma.sync.aligned.m16n8k16.row.col.f32.f16.f16.f32 "
        "{%0,%1,%2,%3}, {%4,%5,%6,%7}, {%8,%9}, {%0,%1,%2,%3};"
        : "+f"(d[0]), "+f"(d[1]), "+f"(d[2]), "+f"(d[3])
        : "r"(a[0]), "r"(a[1]), "r"(a[2]), "r"(a[3]), "r"(b0), "r"(b1));
}

#define LDSM_X4(r0, r1, r2, r3, addr) \
    asm volatile("ldmatrix.sync.aligned.m8n8.x4.shared.b16 {%0,%1,%2,%3}, [%4];" \
        : "=r"(r0), "=r"(r1), "=r"(r2), "=r"(r3) : "r"(addr))

#define CP_ASYNC16(dst, src) \
    asm volatile("cp.async.cg.shared.global [%0], [%1], 16;" \
        :: "r"(dst), "l"(src))
#define CP_COMMIT() asm volatile("cp.async.commit_group;")
#define CP_WAIT(n)  asm volatile("cp.async.wait_group %0;" :: "n"(n))

// ---------------------------------------------------------------------------
// Pre/post kernels (unchanged)
// ---------------------------------------------------------------------------
__global__ __launch_bounds__(256) void cvt16_kernel(
    const float* __restrict__ src, __half* __restrict__ dst, int n4)
{
    int i = blockIdx.x * blockDim.x + threadIdx.x;
    if (i >= n4) return;
    float4 v = ((const float4*)src)[i];
    uint2 u;
    u.x = cvt_h2(v.x, v.y);
    u.y = cvt_h2(v.z, v.w);
    ((uint2*)dst)[i] = u;
}

__global__ __launch_bounds__(256) void split16_kernel(
    const float* __restrict__ src, __half* __restrict__ h,
    __half* __restrict__ l, int n4)
{
    int i = blockIdx.x * blockDim.x + threadIdx.x;
    if (i >= n4) return;
    float4 v = ((const float4*)src)[i];
    __half h0, h1, h2, h3, l0, l1, l2, l3;
    split_h16(v.x, h0, l0); split_h16(v.y, h1, l1);
    split_h16(v.z, h2, l2); split_h16(v.w, h3, l3);
    uint2 uh; uh.x = pack_h2(h0, h1); uh.y = pack_h2(h2, h3);
    uint2 ul; ul.x = pack_h2(l0, l1); ul.y = pack_h2(l2, l3);
    ((uint2*)h)[i] = uh;
    ((uint2*)l)[i] = ul;
}

// Fused RMSNorm + RoPE. Q -> single fp16; K -> fp16 hi/lo.
__global__ __launch_bounds__(256) void normrope_split_kernel(
    const float* __restrict__ qkv,
    const float* __restrict__ qw, const float* __restrict__ kw,
    const int* __restrict__ positions,
    __half* __restrict__ q_g,
    __half* __restrict__ kh_g, __half* __restrict__ kl_g, int T)
{
    const int warp = (blockIdx.x * blockDim.x + threadIdx.x) >> 5;
    const int lane = threadIdx.x & 31;
    if (warp >= T * 24) return;
    const int t = warp / 24;
    const int h = warp % 24;

    const float* x = qkv + (size_t)t * QKV_COLS + h * HEAD_DIM;
    const float* nw = (h < 16) ? qw : kw;

    float v0 = x[lane], v1 = x[lane + 32], v2 = x[lane + 64], v3 = x[lane + 96];
    float ss = v0 * v0 + v1 * v1 + v2 * v2 + v3 * v3;
    #pragma unroll
    for (int o = 16; o; o >>= 1) ss += __shfl_xor_sync(0xffffffffu, ss, o);
    const float rn = rsqrtf(ss * (1.0f / HEAD_DIM) + RMS_EPS);

    float n0 = v0 * rn * nw[lane];
    float n1 = v1 * rn * nw[lane + 32];
    float n2 = v2 * rn * nw[lane + 64];
    float n3 = v3 * rn * nw[lane + 96];

    const double pos = (double)positions[t];
    const double LOG_THETA = 13.815510557964274;
    double f0 = exp(-((double)(2 * lane) / 128.0) * LOG_THETA);
    double f1 = exp(-((double)(2 * (lane + 32)) / 128.0) * LOG_THETA);
    double s0d, c0d, s1d, c1d;
    sincos(pos * f0, &s0d, &c0d);
    sincos(pos * f1, &s1d, &c1d);
    float c0 = (float)c0d, s0 = (float)s0d, c1 = (float)c1d, s1 = (float)s1d;

    float r0 = n0 * c0 - n2 * s0;
    float r2 = n2 * c0 + n0 * s0;
    float r1 = n1 * c1 - n3 * s1;
    float r3 = n3 * c1 + n1 * s1;

    if (h < 16) {
        size_t base = (size_t)t * Q_SIZE + h * HEAD_DIM;
        q_g[base + lane]      = __float2half_rn(r0);
        q_g[base + lane + 32] = __float2half_rn(r1);
        q_g[base + lane + 64] = __float2half_rn(r2);
        q_g[base + lane + 96] = __float2half_rn(r3);
    } else {
        size_t base = (size_t)(h - 16) * T * HEAD_DIM + (size_t)t * HEAD_DIM;
        __half h0, l0, h1, l1, h2, l2, h3, l3;
        split_h16(r0, h0, l0); split_h16(r1, h1, l1);
        split_h16(r2, h2, l2); split_h16(r3, h3, l3);
        kh_g[base + lane] = h0;      kl_g[base + lane] = l0;
        kh_g[base + lane + 32] = h1; kl_g[base + lane + 32] = l1;
        kh_g[base + lane + 64] = h2; kl_g[base + lane + 64] = l2;
        kh_g[base + lane + 96] = h3; kl_g[base + lane + 96] = l3;
    }
}

__global__ void vtrans_kernel(
    const float* __restrict__ qkv, __half* __restrict__ vh, int T)
{
    __shared__ float tile[32][33];
    const int kvh = blockIdx.z;
    const int d0 = blockIdx.y * 32;
    const int t0 = blockIdx.x * 32;
    for (int j = threadIdx.y; j < 32; j += 8) {
        tile[j][threadIdx.x] = qkv[(size_t)(t0 + j) * QKV_COLS + Q_SIZE + KV_SIZE
                                   + kvh * HEAD_DIM + d0 + threadIdx.x];
    }
    __syncthreads();
    for (int j = threadIdx.y; j < 32; j += 8) {
        float v = tile[threadIdx.x][j];
        size_t o = (size_t)kvh * HEAD_DIM * T + (size_t)(d0 + j) * T + t0 + threadIdx.x;
        vh[o] = __float2half_rn(v);
    }
}

// ---------------------------------------------------------------------------
// fp16 HMMA GEMM, 2 combos (unchanged)
// ---------------------------------------------------------------------------
#define XBM 128
#define XBN 128
#define XBK 32
#define XSTR 40
#define STAGE_E (XBM * XSTR)
#define GEMM_SMEM (6 * STAGE_E * 2)

__global__ __launch_bounds__(256, 2) void gemm_f16s(
    const __half* __restrict__ A,
    const __half* __restrict__ Bh, const __half* __restrict__ Bl,
    float* __restrict__ C, int M, int N, int K)
{
    extern __shared__ __half smg[];
    const uint32_t smb = smem_to_u32(smg);

    const int tid  = threadIdx.x;
    const int lane = tid & 31;
    const int wid  = tid >> 5;
    const int gid  = lane >> 2;
    const int tq   = lane & 3;
    const int wm   = (wid & 3) * 32;
    const int wn   = (wid >> 2) * 64;

    const int arow  = lane & 15;
    const int acol8 = (lane >> 4) << 3;
    const int brow  = ((lane >> 4) << 3) + (lane & 7);
    const int bcol8 = ((lane >> 3) & 1) << 3;

    const int bm = blockIdx.y * XBM;
    const int bn = blockIdx.x * XBN;

    #define G_ISSUE(stage, k0) do { \
        uint32_t sb0 = smb + (uint32_t)(stage) * 3 * STAGE_E * 2; \
        _Pragma("unroll") \
        for (int j = 0; j < 2; j++) { \
            int id = tid + j * 256; \
            int r = id >> 2, c = (id & 3) * 8; \
            size_t aoff = (size_t)(bm + r) * K + (k0) + c; \
            size_t boff = (size_t)(bn + r) * K + (k0) + c; \
            uint32_t doff = (uint32_t)(r * XSTR + c) * 2; \
            CP_ASYNC16(sb0 + doff, A + aoff); \
            CP_ASYNC16(sb0 + STAGE_E * 2 + doff, Bh + boff); \
            CP_ASYNC16(sb0 + 2 * STAGE_E * 2 + doff, Bl + boff); \
        } \
    } while (0)

    float acc[2][8][4] = {};

    G_ISSUE(0, 0);
    CP_COMMIT();

    int stage = 0;
    for (int k0 = 0; k0 < K; k0 += XBK, stage ^= 1) {
        if (k0 + XBK < K) {
            G_ISSUE(stage ^ 1, k0 + XBK);
            CP_COMMIT();
            CP_WAIT(1);
        } else {
            CP_WAIT(0);
        }
        __syncthreads();

        const uint32_t sA  = smb + (uint32_t)stage * 3 * STAGE_E * 2;
        const uint32_t sBh = sA + STAGE_E * 2;
        const uint32_t sBl = sBh + STAGE_E * 2;

        #pragma unroll
        for (int kk = 0; kk < XBK; kk += 16) {
            uint32_t a[2][4];
            #pragma unroll
            for (int mt = 0; mt < 2; mt++) {
                uint32_t aoff = (uint32_t)((wm + mt * 16 + arow) * XSTR + kk + acol8) * 2;
                LDSM_X4(a[mt][0], a[mt][1], a[mt][2], a[mt][3], sA + aoff);
            }
            #pragma unroll
            for (int p = 0; p < 4; p++) {
                uint32_t boff = (uint32_t)((wn + p * 16 + brow) * XSTR + kk + bcol8) * 2;
                uint32_t bh0, bh1, bh2, bh3, bl0, bl1, bl2, bl3;
                LDSM_X4(bh0, bh1, bh2, bh3, sBh + boff);
                LDSM_X4(bl0, bl1, bl2, bl3, sBl + boff);
                #pragma unroll
                for (int mt = 0; mt < 2; mt++) {
                    mma_f16(acc[mt][2 * p], a[mt], bh0, bh1);
                    mma_f16(acc[mt][2 * p], a[mt], bl0, bl1);
                    mma_f16(acc[mt][2 * p + 1], a[mt], bh2, bh3);
                    mma_f16(acc[mt][2 * p + 1], a[mt], bl2, bl3);
                }
            }
        }
        __syncthreads();
    }

    #pragma unroll
    for (int mt = 0; mt < 2; mt++) {
        int row = bm + wm + mt * 16 + gid;
        #pragma unroll
        for (int nt = 0; nt < 8; nt++) {
            int col = bn + wn + nt * 8 + tq * 2;
            *(float2*)&C[(size_t)row * N + col] =
                make_float2(acc[mt][nt][0], acc[mt][nt][1]);
            *(float2*)&C[(size_t)(row + 8) * N + col] =
                make_float2(acc[mt][nt][2], acc[mt][nt][3]);
        }
    }
}

// ---------------------------------------------------------------------------
// fp16 HMMA flash attention — q block 128, kv tile 32, 256 threads
// (8 warps x 16 rows), 2 CTAs/SM = 16 warps/SM (GEMM-parity occupancy).
// Q in dedicated smem, fragment reloaded per kt. QK 2 combos; PV 1 combo.
// Double-buffered, one sync per iteration.
// ---------------------------------------------------------------------------
#define AQB 128                         // q rows per CTA
#define AKB 32                          // kv rows per tile
#define SSTR 136                        // K/Q row stride (128 d + 8 pad)
#define VSTR 40                         // V row stride (32 t + 8 pad)
#define QT_B (AQB * SSTR * 2)           // 34816 B (Q buffer)
#define KT_B (AKB * SSTR * 2)           // 8704 B per K buffer
#define VT_B (HEAD_DIM * VSTR * 2)      // 10240 B per V buffer
// layout: Q | K0h K0l K1h K1l | V0 V1
#define OFF_Q     0u
#define OFF_K(s)  (QT_B + (uint32_t)(s) * 2u * KT_B)
#define OFF_KL(s) (OFF_K(s) + KT_B)
#define OFF_V(s)  (QT_B + 4u * KT_B + (uint32_t)(s) * VT_B)
#define ATT_SMEM  (QT_B + 4 * KT_B + 2 * VT_B)   // 90112 B

__global__ __launch_bounds__(256, 2) void attn_mma(
    const __half* __restrict__ q_g,
    const __half* __restrict__ kh_g, const __half* __restrict__ kl_g,
    const __half* __restrict__ v_g,
    __half* __restrict__ attn_out, int T)
{
    extern __shared__ char sm[];
    const uint32_t smb = smem_to_u32(sm);
    const int tid  = threadIdx.x;
    const int lane = tid & 31;
    const int wid  = tid >> 5;          // 0..7
    const int gid  = lane >> 2;
    const int tq   = lane & 3;

    const int qb   = (gridDim.x - 1) - blockIdx.x;   // big blocks first
    const int head = blockIdx.y;
    const int kvh  = head >> 1;
    const int q0   = qb * AQB;
    const int wrow = wid * 16;
    const int iters = 4 * qb + 4;

    const int arow  = lane & 15;
    const int acol8 = (lane >> 4) << 3;
    const int brow  = ((lane >> 4) << 3) + (lane & 7);
    const int bcol8 = ((lane >> 3) & 1) << 3;

    const size_t kbase = (size_t)kvh * T * HEAD_DIM;
    const size_t vbase = (size_t)kvh * HEAD_DIM * T;

    // Prefetch kv tile `itn` into stage itn&1. (256 threads: 2 iters)
    #define ATT_PREFETCH(itn) do { \
        const int st_ = (itn) & 1; \
        const uint32_t khb_ = smb + OFF_K(st_); \
        const uint32_t klb_ = smb + OFF_KL(st_); \
        const uint32_t vb_  = smb + OFF_V(st_); \
        const size_t ko_ = kbase + (size_t)(itn) * AKB * HEAD_DIM; \
        const size_t vo_ = vbase + (size_t)(itn) * AKB; \
        _Pragma("unroll") \
        for (int j = 0; j < 2; j++) { \
            int i = tid + j * 256; \
            int r_ = i >> 4, c_ = (i & 15) << 3; \
            uint32_t doff_ = (uint32_t)(r_ * SSTR + c_) * 2; \
            CP_ASYNC16(khb_ + doff_, kh_g + ko_ + (size_t)r_ * HEAD_DIM + c_); \
            CP_ASYNC16(klb_ + doff_, kl_g + ko_ + (size_t)r_ * HEAD_DIM + c_); \
            int d_ = i >> 2, vc_ = (i & 3) << 3; \
            uint32_t vdoff_ = (uint32_t)(d_ * VSTR + vc_) * 2; \
            CP_ASYNC16(vb_ + vdoff_, v_g + vo_ + (size_t)d_ * T + vc_); \
        } \
        CP_COMMIT(); \
    } while (0)

    // ---- Prologue: prefetch tile 0; stage Q into dedicated buffer ----
    ATT_PREFETCH(0);
    for (int i = tid; i < 1024; i += 256) {
        int r = i >> 3, c = (i & 7) << 4;   // 128 rows x 8 chunks of 16
        uint32_t doff = (uint32_t)(r * SSTR + c) * 2;
        size_t o = (size_t)(q0 + r) * Q_SIZE + head * HEAD_DIM + c;
        *(uint4*)(sm + OFF_Q + doff)      = *(const uint4*)&q_g[o];
        *(uint4*)(sm + OFF_Q + doff + 16) = *(const uint4*)&q_g[o + 8];
    }
    __syncthreads();

    const uint32_t q_sm = smb + OFF_Q;
    const int grow0 = q0 + wrow + gid;
    const int grow1 = grow0 + 8;

    float m0 = -1e30f, m1 = -1e30f, l0s = 0.0f, l1s = 0.0f;
    float o[16][4] = {};

    for (int it = 0; it < iters; it++) {
        const int k0 = it * AKB;
        const int st = it & 1;
        const uint32_t kh_b = smb + OFF_K(st);
        const uint32_t kl_b = smb + OFF_KL(st);
        const uint32_t v_b  = smb + OFF_V(st);

        CP_WAIT(0);
        __syncthreads();

        if (it + 1 < iters) ATT_PREFETCH(it + 1);

        // ---- S = Q K^T (2 combos): warp 16 x 32; Q frag reloaded per kt ----
        float s[4][4];
        #pragma unroll
        for (int nt = 0; nt < 4; nt++)
            #pragma unroll
            for (int c = 0; c < 4; c++) s[nt][c] = 0.0f;

        #pragma unroll
        for (int kt = 0; kt < 8; kt++) {
            uint32_t qf[4];
            uint32_t aoff = (uint32_t)((wrow + arow) * SSTR + kt * 16 + acol8) * 2;
            LDSM_X4(qf[0], qf[1], qf[2], qf[3], q_sm + aoff);
            #pragma unroll
            for (int p = 0; p < 2; p++) {
                uint32_t boff = (uint32_t)((p * 16 + brow) * SSTR + kt * 16 + bcol8) * 2;
                uint32_t bh0, bh1, bh2, bh3, bl0, bl1, bl2, bl3;
                LDSM_X4(bh0, bh1, bh2, bh3, kh_b + boff);
                LDSM_X4(bl0, bl1, bl2, bl3, kl_b + boff);
                mma_f16(s[2 * p], qf, bh0, bh1);
                mma_f16(s[2 * p], qf, bl0, bl1);
                mma_f16(s[2 * p + 1], qf, bh2, bh3);
                mma_f16(s[2 * p + 1], qf, bl2, bl3);
            }
        }

        // ---- scale (log2-domain) + mask + online softmax ----
        const bool diag = (it >= 4 * qb);
        float mx0 = m0, mx1 = m1;
        #pragma unroll
        for (int nt = 0; nt < 4; nt++) {
            int colb = k0 + nt * 8 + tq * 2;
            #pragma unroll
            for (int c = 0; c < 2; c++) {
                float v0 = s[nt][c] * SCALE_L2E;
                float v1 = s[nt][c + 2] * SCALE_L2E;
                if (diag && (colb + c > grow0)) v0 = -1e30f;
                if (diag && (colb + c > grow1)) v1 = -1e30f;
                s[nt][c] = v0; s[nt][c + 2] = v1;
                mx0 = fmaxf(mx0, v0); mx1 = fmaxf(mx1, v1);
            }
        }
        mx0 = fmaxf(mx0, __shfl_xor_sync(0xffffffffu, mx0, 1));
        mx0 = fmaxf(mx0, __shfl_xor_sync(0xffffffffu, mx0, 2));
        mx1 = fmaxf(mx1, __shfl_xor_sync(0xffffffffu, mx1, 1));
        mx1 = fmaxf(mx1, __shfl_xor_sync(0xffffffffu, mx1, 2));

        const float a0 = ex2f(m0 - mx0);
        const float a1 = ex2f(m1 - mx1);
        m0 = mx0; m1 = mx1;

        float sum0 = 0.0f, sum1 = 0.0f;
        #pragma unroll
        for (int nt = 0; nt < 4; nt++) {
            #pragma unroll
            for (int c = 0; c < 2; c++) {
                float p0 = ex2f(s[nt][c] - m0);
                float p1 = ex2f(s[nt][c + 2] - m1);
                s[nt][c] = p0; s[nt][c + 2] = p1;
                sum0 += p0; sum1 += p1;
            }
        }
        sum0 += __shfl_xor_sync(0xffffffffu, sum0, 1);
        sum0 += __shfl_xor_sync(0xffffffffu, sum0, 2);
        sum1 += __shfl_xor_sync(0xffffffffu, sum1, 1);
        sum1 += __shfl_xor_sync(0xffffffffu, sum1, 2);
        l0s = l0s * a0 + sum0;
        l1s = l1s * a1 + sum1;

        #pragma unroll
        for (int nt = 0; nt < 16; nt++) {
            o[nt][0] *= a0; o[nt][1] *= a0;
            o[nt][2] *= a1; o[nt][3] *= a1;
        }

        // ---- O += P @ V (1 combo): P 16x32, Vt 32x128 ----
        #pragma unroll
        for (int kt = 0; kt < 2; kt++) {
            uint32_t ph[4];
            ph[0] = cvt_h2(s[2 * kt][0], s[2 * kt][1]);
            ph[1] = cvt_h2(s[2 * kt][2], s[2 * kt][3]);
            ph[2] = cvt_h2(s[2 * kt + 1][0], s[2 * kt + 1][1]);
            ph[3] = cvt_h2(s[2 * kt + 1][2], s[2 * kt + 1][3]);
            #pragma unroll
            for (int p = 0; p < 8; p++) {
                uint32_t boff = (uint32_t)((p * 16 + brow) * VSTR + kt * 16 + bcol8) * 2;
                uint32_t vh0, vh1, vh2, vh3;
                LDSM_X4(vh0, vh1, vh2, vh3, v_b + boff);
                mma_f16(o[2 * p], ph, vh0, vh1);
                mma_f16(o[2 * p + 1], ph, vh2, vh3);
            }
        }
    }

    // ---- Epilogue: normalize, store single fp16 ----
    const float inv0 = 1.0f / l0s;
    const float inv1 = 1.0f / l1s;
    #pragma unroll
    for (int nt = 0; nt < 16; nt++) {
        int dcol = head * HEAD_DIM + nt * 8 + tq * 2;
        *(uint32_t*)&attn_out[(size_t)grow0 * Q_SIZE + dcol] =
            cvt_h2(o[nt][0] * inv0, o[nt][1] * inv0);
        *(uint32_t*)&attn_out[(size_t)grow1 * Q_SIZE + dcol] =
            cvt_h2(o[nt][2] * inv1, o[nt][3] * inv1);
    }
}

// ---------------------------------------------------------------------------
// Launch
// ---------------------------------------------------------------------------
extern "C" void kernel_launch(void* const* d_in, const int* in_sizes, int n_in,
                              void* d_out, int out_size)
{
    const float* hidden = (const float*)d_in[0];
    const float* qkv_w  = (const float*)d_in[1];
    const float* q_nw   = (const float*)d_in[2];
    const float* k_nw   = (const float*)d_in[3];
    const float* o_w    = (const float*)d_in[4];
    const int*   pos    = (const int*)d_in[5];
    float* out = (float*)d_out;

    const int T = in_sizes[0] / HIDDEN;

    float* qkv;  cudaGetSymbolAddress((void**)&qkv,  g_qkv);
    __half *hid, *w1_h, *w1_l, *w2_h, *w2_l, *at;
    __half *q, *k_h, *k_l, *v;
    cudaGetSymbolAddress((void**)&hid,  g_hid);
    cudaGetSymbolAddress((void**)&w1_h, g_w1_h);
    cudaGetSymbolAddress((void**)&w1_l, g_w1_l);
    cudaGetSymbolAddress((void**)&w2_h, g_w2_h);
    cudaGetSymbolAddress((void**)&w2_l, g_w2_l);
    cudaGetSymbolAddress((void**)&at,   g_at);
    cudaGetSymbolAddress((void**)&q,    g_q);
    cudaGetSymbolAddress((void**)&k_h,  g_k_h);
    cudaGetSymbolAddress((void**)&k_l,  g_k_l);
    cudaGetSymbolAddress((void**)&v,    g_v);

    cudaFuncSetAttribute(attn_mma, cudaFuncAttributeMaxDynamicSharedMemorySize,
                         ATT_SMEM);
    cudaFuncSetAttribute(gemm_f16s, cudaFuncAttributeMaxDynamicSharedMemorySize,
                         GEMM_SMEM);

    // 0) Convert/split inputs
    {
        int n4 = T * HIDDEN / 4;
        cvt16_kernel<<<(n4 + 255) / 256, 256>>>(hidden, hid, n4);
        n4 = QKV_COLS * HIDDEN / 4;
        split16_kernel<<<(n4 + 255) / 256, 256>>>(qkv_w, w1_h, w1_l, n4);
        n4 = HIDDEN * Q_SIZE / 4;
        split16_kernel<<<(n4 + 255) / 256, 256>>>(o_w, w2_h, w2_l, n4);
    }
    // 1) QKV projection
    {
        dim3 grid(QKV_COLS / XBN, T / XBM);
        gemm_f16s<<<grid, 256, GEMM_SMEM>>>(hid, w1_h, w1_l, qkv,
                                            T, QKV_COLS, HIDDEN);
    }
    // 2) Fused RMSNorm + RoPE + split (Q single, K hi/lo); transpose V
    {
        int warps = T * 24;
        int blocks = (warps + 7) / 8;
        normrope_split_kernel<<<blocks, 256>>>(qkv, q_nw, k_nw, pos,
                                               q, k_h, k_l, T);
        dim3 vg(T / 32, HEAD_DIM / 32, NUM_KV);
        vtrans_kernel<<<vg, dim3(32, 8)>>>(qkv, v, T);
    }
    // 3) Attention (q128 x kv32, 256 threads, 2 CTAs/SM = 16 warps/SM)
    {
        dim3 grid(T / AQB, NUM_HEADS);
        attn_mma<<<grid, 256, ATT_SMEM>>>(q, k_h, k_l, v, at, T);
    }
    // 4) Output projection
    {
        dim3 grid(HIDDEN / XBN, T / XBM);
        gemm_f16s<<<grid, 256, GEMM_SMEM>>>(at, w2_h, w2_l, out,
                                            T, HIDDEN, HIDDEN);
    }
}

// round 14
// speedup vs baseline: 1.1075x; 1.1075x over previous
#include <cuda_runtime.h>
#include <cuda_bf16.h>
#include <cuda_fp16.h>
#include <math.h>
#include <float.h>
#include <cstdint>

// Problem constants
#define HIDDEN    2048
#define NUM_HEADS 16
#define NUM_KV    8
#define HEAD_DIM  128
#define Q_SIZE    (NUM_HEADS * HEAD_DIM)        // 2048
#define KV_SIZE   (NUM_KV * HEAD_DIM)           // 1024
#define QKV_COLS  (Q_SIZE + 2 * KV_SIZE)        // 4096
#define SCALE     0.08838834764831845f          // 128^-0.5
#define SCALE_L2E 0.12751985675839602f          // SCALE * log2(e)
#define RMS_EPS   1e-6f

#define MAX_T 4096

// Scratch (static device globals)
__device__ float g_qkv[(size_t)MAX_T * QKV_COLS];
__device__ __half g_hid[(size_t)MAX_T * HIDDEN];
__device__ __half g_w1_h[(size_t)QKV_COLS * HIDDEN];
__device__ __half g_w1_l[(size_t)QKV_COLS * HIDDEN];
__device__ __half g_w2_h[(size_t)HIDDEN * Q_SIZE];
__device__ __half g_w2_l[(size_t)HIDDEN * Q_SIZE];
__device__ __half g_at[(size_t)MAX_T * Q_SIZE];
__device__ __half g_q[(size_t)MAX_T * Q_SIZE];              // single fp16 Q
__device__ __half g_k[(size_t)NUM_KV * MAX_T * HEAD_DIM];   // single fp16 K
__device__ __half g_v[(size_t)NUM_KV * HEAD_DIM * MAX_T];   // [kvh][d][t]

// ===========================================================================
// Helpers
// ===========================================================================
__device__ __forceinline__ uint32_t smem_to_u32(const void* p) {
    uint32_t a;
    asm("{ .reg .u64 t; cvta.to.shared.u64 t, %1; cvt.u32.u64 %0, t; }"
        : "=r"(a) : "l"(p));
    return a;
}
__device__ __forceinline__ void split_h16(float x, __half& h, __half& l) {
    h = __float2half_rn(x);
    l = __float2half_rn(x - __half2float(h));
}
__device__ __forceinline__ float ex2f(float x) {
    float r;
    asm("ex2.approx.f32 %0, %1;" : "=f"(r) : "f"(x));
    return r;
}
__device__ __forceinline__ uint32_t cvt_h2(float a, float b) {
    uint32_t r;
    asm("cvt.rn.f16x2.f32 %0, %1, %2;" : "=r"(r) : "f"(b), "f"(a));
    return r;
}
__device__ __forceinline__ uint32_t pack_h2(__half a, __half b) {
    __half2 t = __halves2half2(a, b);
    return *reinterpret_cast<uint32_t*>(&t);
}

__device__ __forceinline__ void mma_f16(float* d, const uint32_t* a,
                                        uint32_t b0, uint32_t b1) {
    asm volatile(
        "mma.sync.aligned.m16n8k16.row.col.f32.f16.f16.f32 "
        "{%0,%1,%2,%3}, {%4,%5,%6,%7}, {%8,%9}, {%0,%1,%2,%3};"
        : "+f"(d[0]), "+f"(d[1]), "+f"(d[2]), "+f"(d[3])
        : "r"(a[0]), "r"(a[1]), "r"(a[2]), "r"(a[3]), "r"(b0), "r"(b1));
}

#define LDSM_X4(r0, r1, r2, r3, addr) \
    asm volatile("ldmatrix.sync.aligned.m8n8.x4.shared.b16 {%0,%1,%2,%3}, [%4];" \
        : "=r"(r0), "=r"(r1), "=r"(r2), "=r"(r3) : "r"(addr))

#define CP_ASYNC16(dst, src) \
    asm volatile("cp.async.cg.shared.global [%0], [%1], 16;" \
        :: "r"(dst), "l"(src))
#define CP_COMMIT() asm volatile("cp.async.commit_group;")
#define CP_WAIT(n)  asm volatile("cp.async.wait_group %0;" :: "n"(n))

// ---------------------------------------------------------------------------
// Pre/post kernels
// ---------------------------------------------------------------------------
__global__ __launch_bounds__(256) void cvt16_kernel(
    const float* __restrict__ src, __half* __restrict__ dst, int n4)
{
    int i = blockIdx.x * blockDim.x + threadIdx.x;
    if (i >= n4) return;
    float4 v = ((const float4*)src)[i];
    uint2 u;
    u.x = cvt_h2(v.x, v.y);
    u.y = cvt_h2(v.z, v.w);
    ((uint2*)dst)[i] = u;
}

__global__ __launch_bounds__(256) void split16_kernel(
    const float* __restrict__ src, __half* __restrict__ h,
    __half* __restrict__ l, int n4)
{
    int i = blockIdx.x * blockDim.x + threadIdx.x;
    if (i >= n4) return;
    float4 v = ((const float4*)src)[i];
    __half h0, h1, h2, h3, l0, l1, l2, l3;
    split_h16(v.x, h0, l0); split_h16(v.y, h1, l1);
    split_h16(v.z, h2, l2); split_h16(v.w, h3, l3);
    uint2 uh; uh.x = pack_h2(h0, h1); uh.y = pack_h2(h2, h3);
    uint2 ul; ul.x = pack_h2(l0, l1); ul.y = pack_h2(l2, l3);
    ((uint2*)h)[i] = uh;
    ((uint2*)l)[i] = ul;
}

// Fused RMSNorm + RoPE. Q and K -> single fp16.
__global__ __launch_bounds__(256) void normrope_split_kernel(
    const float* __restrict__ qkv,
    const float* __restrict__ qw, const float* __restrict__ kw,
    const int* __restrict__ positions,
    __half* __restrict__ q_g, __half* __restrict__ k_g, int T)
{
    const int warp = (blockIdx.x * blockDim.x + threadIdx.x) >> 5;
    const int lane = threadIdx.x & 31;
    if (warp >= T * 24) return;
    const int t = warp / 24;
    const int h = warp % 24;

    const float* x = qkv + (size_t)t * QKV_COLS + h * HEAD_DIM;
    const float* nw = (h < 16) ? qw : kw;

    float v0 = x[lane], v1 = x[lane + 32], v2 = x[lane + 64], v3 = x[lane + 96];
    float ss = v0 * v0 + v1 * v1 + v2 * v2 + v3 * v3;
    #pragma unroll
    for (int o = 16; o; o >>= 1) ss += __shfl_xor_sync(0xffffffffu, ss, o);
    const float rn = rsqrtf(ss * (1.0f / HEAD_DIM) + RMS_EPS);

    float n0 = v0 * rn * nw[lane];
    float n1 = v1 * rn * nw[lane + 32];
    float n2 = v2 * rn * nw[lane + 64];
    float n3 = v3 * rn * nw[lane + 96];

    const double pos = (double)positions[t];
    const double LOG_THETA = 13.815510557964274;
    double f0 = exp(-((double)(2 * lane) / 128.0) * LOG_THETA);
    double f1 = exp(-((double)(2 * (lane + 32)) / 128.0) * LOG_THETA);
    double s0d, c0d, s1d, c1d;
    sincos(pos * f0, &s0d, &c0d);
    sincos(pos * f1, &s1d, &c1d);
    float c0 = (float)c0d, s0 = (float)s0d, c1 = (float)c1d, s1 = (float)s1d;

    float r0 = n0 * c0 - n2 * s0;
    float r2 = n2 * c0 + n0 * s0;
    float r1 = n1 * c1 - n3 * s1;
    float r3 = n3 * c1 + n1 * s1;

    __half* dst;
    size_t base;
    if (h < 16) {
        base = (size_t)t * Q_SIZE + h * HEAD_DIM;
        dst = q_g;
    } else {
        base = (size_t)(h - 16) * T * HEAD_DIM + (size_t)t * HEAD_DIM;
        dst = k_g;
    }
    dst[base + lane]      = __float2half_rn(r0);
    dst[base + lane + 32] = __float2half_rn(r1);
    dst[base + lane + 64] = __float2half_rn(r2);
    dst[base + lane + 96] = __float2half_rn(r3);
}

__global__ void vtrans_kernel(
    const float* __restrict__ qkv, __half* __restrict__ vh, int T)
{
    __shared__ float tile[32][33];
    const int kvh = blockIdx.z;
    const int d0 = blockIdx.y * 32;
    const int t0 = blockIdx.x * 32;
    for (int j = threadIdx.y; j < 32; j += 8) {
        tile[j][threadIdx.x] = qkv[(size_t)(t0 + j) * QKV_COLS + Q_SIZE + KV_SIZE
                                   + kvh * HEAD_DIM + d0 + threadIdx.x];
    }
    __syncthreads();
    for (int j = threadIdx.y; j < 32; j += 8) {
        float v = tile[threadIdx.x][j];
        size_t o = (size_t)kvh * HEAD_DIM * T + (size_t)(d0 + j) * T + t0 + threadIdx.x;
        vh[o] = __float2half_rn(v);
    }
}

// ---------------------------------------------------------------------------
// fp16 HMMA GEMM, 2 combos (unchanged)
// ---------------------------------------------------------------------------
#define XBM 128
#define XBN 128
#define XBK 32
#define XSTR 40
#define STAGE_E (XBM * XSTR)
#define GEMM_SMEM (6 * STAGE_E * 2)

__global__ __launch_bounds__(256, 2) void gemm_f16s(
    const __half* __restrict__ A,
    const __half* __restrict__ Bh, const __half* __restrict__ Bl,
    float* __restrict__ C, int M, int N, int K)
{
    extern __shared__ __half smg[];
    const uint32_t smb = smem_to_u32(smg);

    const int tid  = threadIdx.x;
    const int lane = tid & 31;
    const int wid  = tid >> 5;
    const int gid  = lane >> 2;
    const int tq   = lane & 3;
    const int wm   = (wid & 3) * 32;
    const int wn   = (wid >> 2) * 64;

    const int arow  = lane & 15;
    const int acol8 = (lane >> 4) << 3;
    const int brow  = ((lane >> 4) << 3) + (lane & 7);
    const int bcol8 = ((lane >> 3) & 1) << 3;

    const int bm = blockIdx.y * XBM;
    const int bn = blockIdx.x * XBN;

    #define G_ISSUE(stage, k0) do { \
        uint32_t sb0 = smb + (uint32_t)(stage) * 3 * STAGE_E * 2; \
        _Pragma("unroll") \
        for (int j = 0; j < 2; j++) { \
            int id = tid + j * 256; \
            int r = id >> 2, c = (id & 3) * 8; \
            size_t aoff = (size_t)(bm + r) * K + (k0) + c; \
            size_t boff = (size_t)(bn + r) * K + (k0) + c; \
            uint32_t doff = (uint32_t)(r * XSTR + c) * 2; \
            CP_ASYNC16(sb0 + doff, A + aoff); \
            CP_ASYNC16(sb0 + STAGE_E * 2 + doff, Bh + boff); \
            CP_ASYNC16(sb0 + 2 * STAGE_E * 2 + doff, Bl + boff); \
        } \
    } while (0)

    float acc[2][8][4] = {};

    G_ISSUE(0, 0);
    CP_COMMIT();

    int stage = 0;
    for (int k0 = 0; k0 < K; k0 += XBK, stage ^= 1) {
        if (k0 + XBK < K) {
            G_ISSUE(stage ^ 1, k0 + XBK);
            CP_COMMIT();
            CP_WAIT(1);
        } else {
            CP_WAIT(0);
        }
        __syncthreads();

        const uint32_t sA  = smb + (uint32_t)stage * 3 * STAGE_E * 2;
        const uint32_t sBh = sA + STAGE_E * 2;
        const uint32_t sBl = sBh + STAGE_E * 2;

        #pragma unroll
        for (int kk = 0; kk < XBK; kk += 16) {
            uint32_t a[2][4];
            #pragma unroll
            for (int mt = 0; mt < 2; mt++) {
                uint32_t aoff = (uint32_t)((wm + mt * 16 + arow) * XSTR + kk + acol8) * 2;
                LDSM_X4(a[mt][0], a[mt][1], a[mt][2], a[mt][3], sA + aoff);
            }
            #pragma unroll
            for (int p = 0; p < 4; p++) {
                uint32_t boff = (uint32_t)((wn + p * 16 + brow) * XSTR + kk + bcol8) * 2;
                uint32_t bh0, bh1, bh2, bh3, bl0, bl1, bl2, bl3;
                LDSM_X4(bh0, bh1, bh2, bh3, sBh + boff);
                LDSM_X4(bl0, bl1, bl2, bl3, sBl + boff);
                #pragma unroll
                for (int mt = 0; mt < 2; mt++) {
                    mma_f16(acc[mt][2 * p], a[mt], bh0, bh1);
                    mma_f16(acc[mt][2 * p], a[mt], bl0, bl1);
                    mma_f16(acc[mt][2 * p + 1], a[mt], bh2, bh3);
                    mma_f16(acc[mt][2 * p + 1], a[mt], bl2, bl3);
                }
            }
        }
        __syncthreads();
    }

    #pragma unroll
    for (int mt = 0; mt < 2; mt++) {
        int row = bm + wm + mt * 16 + gid;
        #pragma unroll
        for (int nt = 0; nt < 8; nt++) {
            int col = bn + wn + nt * 8 + tq * 2;
            *(float2*)&C[(size_t)row * N + col] =
                make_float2(acc[mt][nt][0], acc[mt][nt][1]);
            *(float2*)&C[(size_t)(row + 8) * N + col] =
                make_float2(acc[mt][nt][2], acc[mt][nt][3]);
        }
    }
}

// ---------------------------------------------------------------------------
// fp16 HMMA flash attention — q block 64, kv tile 64, 128 threads
// (4 warps x 16 rows), 3 CTAs/SM. QK 1 combo (Q, K single fp16);
// PV 1 combo. Persistent Q fragments; Q staged through K0|K1 region.
// Double-buffered, one sync per iteration.
// ---------------------------------------------------------------------------
#define AQB 64                          // q rows per CTA
#define AKB 64                          // kv rows per tile
#define SSTR 136                        // K/Q row stride (128 d + 8 pad)
#define VSTR 72                         // V row stride (64 t + 8 pad)
#define KT_B (AKB * SSTR * 2)           // 17408 B per K buffer
#define VT_B (HEAD_DIM * VSTR * 2)      // 18432 B per V buffer
// layout: K0 K1 V0 V1   (Q staged through K0|K1 = 34816 B in prologue)
#define OFF_K(s)  ((uint32_t)(s) * KT_B)
#define OFF_V(s)  (2u * KT_B + (uint32_t)(s) * VT_B)
#define ATT_SMEM  (2 * KT_B + 2 * VT_B)   // 71680 B -> 3 CTAs/SM

__global__ __launch_bounds__(128, 3) void attn_mma(
    const __half* __restrict__ q_g, const __half* __restrict__ k_g,
    const __half* __restrict__ v_g,
    __half* __restrict__ attn_out, int T)
{
    extern __shared__ char sm[];
    const uint32_t smb = smem_to_u32(sm);
    const int tid  = threadIdx.x;
    const int lane = tid & 31;
    const int wid  = tid >> 5;          // 0..3
    const int gid  = lane >> 2;
    const int tq   = lane & 3;

    const int qb   = (gridDim.x - 1) - blockIdx.x;   // big blocks first
    const int head = blockIdx.y;
    const int kvh  = head >> 1;
    const int q0   = qb * AQB;
    const int wrow = wid * 16;
    const int iters = qb + 1;

    const int arow  = lane & 15;
    const int acol8 = (lane >> 4) << 3;
    const int brow  = ((lane >> 4) << 3) + (lane & 7);
    const int bcol8 = ((lane >> 3) & 1) << 3;

    const size_t kbase = (size_t)kvh * T * HEAD_DIM;
    const size_t vbase = (size_t)kvh * HEAD_DIM * T;

    // Prefetch kv tile `itn` into stage itn&1.
    // K: 64 rows x 128 d = 1024 uint4. V: 128 d x 64 t = 1024 uint4.
    #define ATT_PREFETCH(itn) do { \
        const int st_ = (itn) & 1; \
        const uint32_t kb_ = smb + OFF_K(st_); \
        const uint32_t vb_ = smb + OFF_V(st_); \
        const size_t ko_ = kbase + (size_t)(itn) * AKB * HEAD_DIM; \
        const size_t vo_ = vbase + (size_t)(itn) * AKB; \
        _Pragma("unroll") \
        for (int j = 0; j < 8; j++) { \
            int i = tid + j * 128; \
            int r_ = i >> 4, c_ = (i & 15) << 3; \
            uint32_t doff_ = (uint32_t)(r_ * SSTR + c_) * 2; \
            CP_ASYNC16(kb_ + doff_, k_g + ko_ + (size_t)r_ * HEAD_DIM + c_); \
            int d_ = i >> 3, vc_ = (i & 7) << 3; \
            uint32_t vdoff_ = (uint32_t)(d_ * VSTR + vc_) * 2; \
            CP_ASYNC16(vb_ + vdoff_, v_g + vo_ + (size_t)d_ * T + vc_); \
        } \
        CP_COMMIT(); \
    } while (0)

    // ---- Prologue: stage Q through K0|K1 (contiguous 34816 B), build
    //      persistent frags, THEN prefetch tile 0 (overwrites K0). ----
    for (int i = tid; i < 512; i += 128) {
        int r = i >> 3, c = (i & 7) << 4;   // 64 rows x 8 chunks of 16
        uint32_t doff = (uint32_t)(r * SSTR + c) * 2;
        size_t o = (size_t)(q0 + r) * Q_SIZE + head * HEAD_DIM + c;
        *(uint4*)(sm + doff)      = *(const uint4*)&q_g[o];
        *(uint4*)(sm + doff + 16) = *(const uint4*)&q_g[o + 8];
    }
    __syncthreads();

    uint32_t qh[8][4];
    #pragma unroll
    for (int kt = 0; kt < 8; kt++) {
        uint32_t aoff = (uint32_t)((wrow + arow) * SSTR + kt * 16 + acol8) * 2;
        LDSM_X4(qh[kt][0], qh[kt][1], qh[kt][2], qh[kt][3], smb + aoff);
    }
    __syncthreads();   // all frags built before prefetch overwrites K0

    ATT_PREFETCH(0);

    const int grow0 = q0 + wrow + gid;
    const int grow1 = grow0 + 8;

    float m0 = -1e30f, m1 = -1e30f, l0s = 0.0f, l1s = 0.0f;
    float o[16][4] = {};

    for (int it = 0; it < iters; it++) {
        const int k0 = it * AKB;
        const int st = it & 1;
        const uint32_t k_b = smb + OFF_K(st);
        const uint32_t v_b = smb + OFF_V(st);

        CP_WAIT(0);
        __syncthreads();

        if (it + 1 < iters) ATT_PREFETCH(it + 1);

        // ---- S = Q K^T (1 combo): warp 16 x 64 ----
        float s[8][4];
        #pragma unroll
        for (int nt = 0; nt < 8; nt++)
            #pragma unroll
            for (int c = 0; c < 4; c++) s[nt][c] = 0.0f;

        #pragma unroll
        for (int kt = 0; kt < 8; kt++) {
            #pragma unroll
            for (int p = 0; p < 4; p++) {
                uint32_t boff = (uint32_t)((p * 16 + brow) * SSTR + kt * 16 + bcol8) * 2;
                uint32_t b0, b1, b2, b3;
                LDSM_X4(b0, b1, b2, b3, k_b + boff);
                mma_f16(s[2 * p], qh[kt], b0, b1);
                mma_f16(s[2 * p + 1], qh[kt], b2, b3);
            }
        }

        // ---- scale (log2-domain) + mask + online softmax ----
        const bool diag = (it == qb);
        float mx0 = m0, mx1 = m1;
        #pragma unroll
        for (int nt = 0; nt < 8; nt++) {
            int colb = k0 + nt * 8 + tq * 2;
            #pragma unroll
            for (int c = 0; c < 2; c++) {
                float v0 = s[nt][c] * SCALE_L2E;
                float v1 = s[nt][c + 2] * SCALE_L2E;
                if (diag && (colb + c > grow0)) v0 = -1e30f;
                if (diag && (colb + c > grow1)) v1 = -1e30f;
                s[nt][c] = v0; s[nt][c + 2] = v1;
                mx0 = fmaxf(mx0, v0); mx1 = fmaxf(mx1, v1);
            }
        }
        mx0 = fmaxf(mx0, __shfl_xor_sync(0xffffffffu, mx0, 1));
        mx0 = fmaxf(mx0, __shfl_xor_sync(0xffffffffu, mx0, 2));
        mx1 = fmaxf(mx1, __shfl_xor_sync(0xffffffffu, mx1, 1));
        mx1 = fmaxf(mx1, __shfl_xor_sync(0xffffffffu, mx1, 2));

        const float a0 = ex2f(m0 - mx0);
        const float a1 = ex2f(m1 - mx1);
        m0 = mx0; m1 = mx1;

        float sum0 = 0.0f, sum1 = 0.0f;
        #pragma unroll
        for (int nt = 0; nt < 8; nt++) {
            #pragma unroll
            for (int c = 0; c < 2; c++) {
                float p0 = ex2f(s[nt][c] - m0);
                float p1 = ex2f(s[nt][c + 2] - m1);
                s[nt][c] = p0; s[nt][c + 2] = p1;
                sum0 += p0; sum1 += p1;
            }
        }
        sum0 += __shfl_xor_sync(0xffffffffu, sum0, 1);
        sum0 += __shfl_xor_sync(0xffffffffu, sum0, 2);
        sum1 += __shfl_xor_sync(0xffffffffu, sum1, 1);
        sum1 += __shfl_xor_sync(0xffffffffu, sum1, 2);
        l0s = l0s * a0 + sum0;
        l1s = l1s * a1 + sum1;

        #pragma unroll
        for (int nt = 0; nt < 16; nt++) {
            o[nt][0] *= a0; o[nt][1] *= a0;
            o[nt][2] *= a1; o[nt][3] *= a1;
        }

        // ---- O += P @ V (1 combo): P 16x64, Vt 64x128 ----
        #pragma unroll
        for (int kt = 0; kt < 4; kt++) {
            uint32_t ph[4];
            ph[0] = cvt_h2(s[2 * kt][0], s[2 * kt][1]);
            ph[1] = cvt_h2(s[2 * kt][2], s[2 * kt][3]);
            ph[2] = cvt_h2(s[2 * kt + 1][0], s[2 * kt + 1][1]);
            ph[3] = cvt_h2(s[2 * kt + 1][2], s[2 * kt + 1][3]);
            #pragma unroll
            for (int p = 0; p < 8; p++) {
                uint32_t boff = (uint32_t)((p * 16 + brow) * VSTR + kt * 16 + bcol8) * 2;
                uint32_t v0r, v1r, v2r, v3r;
                LDSM_X4(v0r, v1r, v2r, v3r, v_b + boff);
                mma_f16(o[2 * p], ph, v0r, v1r);
                mma_f16(o[2 * p + 1], ph, v2r, v3r);
            }
        }
    }

    // ---- Epilogue: normalize, store single fp16 ----
    const float inv0 = 1.0f / l0s;
    const float inv1 = 1.0f / l1s;
    #pragma unroll
    for (int nt = 0; nt < 16; nt++) {
        int dcol = head * HEAD_DIM + nt * 8 + tq * 2;
        *(uint32_t*)&attn_out[(size_t)grow0 * Q_SIZE + dcol] =
            cvt_h2(o[nt][0] * inv0, o[nt][1] * inv0);
        *(uint32_t*)&attn_out[(size_t)grow1 * Q_SIZE + dcol] =
            cvt_h2(o[nt][2] * inv1, o[nt][3] * inv1);
    }
}

// ---------------------------------------------------------------------------
// Launch
// ---------------------------------------------------------------------------
extern "C" void kernel_launch(void* const* d_in, const int* in_sizes, int n_in,
                              void* d_out, int out_size)
{
    const float* hidden = (const float*)d_in[0];
    const float* qkv_w  = (const float*)d_in[1];
    const float* q_nw   = (const float*)d_in[2];
    const float* k_nw   = (const float*)d_in[3];
    const float* o_w    = (const float*)d_in[4];
    const int*   pos    = (const int*)d_in[5];
    float* out = (float*)d_out;

    const int T = in_sizes[0] / HIDDEN;

    float* qkv;  cudaGetSymbolAddress((void**)&qkv,  g_qkv);
    __half *hid, *w1_h, *w1_l, *w2_h, *w2_l, *at;
    __half *q, *k, *v;
    cudaGetSymbolAddress((void**)&hid,  g_hid);
    cudaGetSymbolAddress((void**)&w1_h, g_w1_h);
    cudaGetSymbolAddress((void**)&w1_l, g_w1_l);
    cudaGetSymbolAddress((void**)&w2_h, g_w2_h);
    cudaGetSymbolAddress((void**)&w2_l, g_w2_l);
    cudaGetSymbolAddress((void**)&at,   g_at);
    cudaGetSymbolAddress((void**)&q,    g_q);
    cudaGetSymbolAddress((void**)&k,    g_k);
    cudaGetSymbolAddress((void**)&v,    g_v);

    cudaFuncSetAttribute(attn_mma, cudaFuncAttributeMaxDynamicSharedMemorySize,
                         ATT_SMEM);
    cudaFuncSetAttribute(gemm_f16s, cudaFuncAttributeMaxDynamicSharedMemorySize,
                         GEMM_SMEM);

    // 0) Convert/split inputs
    {
        int n4 = T * HIDDEN / 4;
        cvt16_kernel<<<(n4 + 255) / 256, 256>>>(hidden, hid, n4);
        n4 = QKV_COLS * HIDDEN / 4;
        split16_kernel<<<(n4 + 255) / 256, 256>>>(qkv_w, w1_h, w1_l, n4);
        n4 = HIDDEN * Q_SIZE / 4;
        split16_kernel<<<(n4 + 255) / 256, 256>>>(o_w, w2_h, w2_l, n4);
    }
    // 1) QKV projection
    {
        dim3 grid(QKV_COLS / XBN, T / XBM);
        gemm_f16s<<<grid, 256, GEMM_SMEM>>>(hid, w1_h, w1_l, qkv,
                                            T, QKV_COLS, HIDDEN);
    }
    // 2) Fused RMSNorm + RoPE (Q, K single fp16); transpose V
    {
        int warps = T * 24;
        int blocks = (warps + 7) / 8;
        normrope_split_kernel<<<blocks, 256>>>(qkv, q_nw, k_nw, pos, q, k, T);
        dim3 vg(T / 32, HEAD_DIM / 32, NUM_KV);
        vtrans_kernel<<<vg, dim3(32, 8)>>>(qkv, v, T);
    }
    // 3) Attention (q64 x kv64, 3 CTAs/SM, 1-combo QK/PV)
    {
        dim3 grid(T / AQB, NUM_HEADS);
        attn_mma<<<grid, 128, ATT_SMEM>>>(q, k, v, at, T);
    }
    // 4) Output projection
    {
        dim3 grid(HIDDEN / XBN, T / XBM);
        gemm_f16s<<<grid, 256, GEMM_SMEM>>>(at, w2_h, w2_l, out,
                                            T, HIDDEN, HIDDEN);
    }
}

// round 15
// speedup vs baseline: 1.3325x; 1.2032x over previous
#include <cuda_runtime.h>
#include <cuda_bf16.h>
#include <cuda_fp16.h>
#include <math.h>
#include <float.h>
#include <cstdint>

// Problem constants
#define HIDDEN    2048
#define NUM_HEADS 16
#define NUM_KV    8
#define HEAD_DIM  128
#define Q_SIZE    (NUM_HEADS * HEAD_DIM)        // 2048
#define KV_SIZE   (NUM_KV * HEAD_DIM)           // 1024
#define QKV_COLS  (Q_SIZE + 2 * KV_SIZE)        // 4096
#define SCALE     0.08838834764831845f          // 128^-0.5
#define SCALE_L2E 0.12751985675839602f          // SCALE * log2(e)
#define RMS_EPS   1e-6f

#define MAX_T 4096

// Scratch (static device globals)
__device__ float g_qkv[(size_t)MAX_T * QKV_COLS];
__device__ __half g_hid[(size_t)MAX_T * HIDDEN];
__device__ __half g_w1[(size_t)QKV_COLS * HIDDEN];          // single fp16 weights
__device__ __half g_w2[(size_t)HIDDEN * Q_SIZE];
__device__ __half g_at[(size_t)MAX_T * Q_SIZE];
__device__ __half g_q[(size_t)MAX_T * Q_SIZE];              // single fp16 Q
__device__ __half g_k[(size_t)NUM_KV * MAX_T * HEAD_DIM];   // single fp16 K
__device__ __half g_v[(size_t)NUM_KV * HEAD_DIM * MAX_T];   // [kvh][d][t]

// ===========================================================================
// Helpers
// ===========================================================================
__device__ __forceinline__ uint32_t smem_to_u32(const void* p) {
    uint32_t a;
    asm("{ .reg .u64 t; cvta.to.shared.u64 t, %1; cvt.u32.u64 %0, t; }"
        : "=r"(a) : "l"(p));
    return a;
}
__device__ __forceinline__ float ex2f(float x) {
    float r;
    asm("ex2.approx.f32 %0, %1;" : "=f"(r) : "f"(x));
    return r;
}
__device__ __forceinline__ uint32_t cvt_h2(float a, float b) {
    uint32_t r;
    asm("cvt.rn.f16x2.f32 %0, %1, %2;" : "=r"(r) : "f"(b), "f"(a));
    return r;
}

__device__ __forceinline__ void mma_f16(float* d, const uint32_t* a,
                                        uint32_t b0, uint32_t b1) {
    asm volatile(
        "mma.sync.aligned.m16n8k16.row.col.f32.f16.f16.f32 "
        "{%0,%1,%2,%3}, {%4,%5,%6,%7}, {%8,%9}, {%0,%1,%2,%3};"
        : "+f"(d[0]), "+f"(d[1]), "+f"(d[2]), "+f"(d[3])
        : "r"(a[0]), "r"(a[1]), "r"(a[2]), "r"(a[3]), "r"(b0), "r"(b1));
}

#define LDSM_X4(r0, r1, r2, r3, addr) \
    asm volatile("ldmatrix.sync.aligned.m8n8.x4.shared.b16 {%0,%1,%2,%3}, [%4];" \
        : "=r"(r0), "=r"(r1), "=r"(r2), "=r"(r3) : "r"(addr))

#define CP_ASYNC16(dst, src) \
    asm volatile("cp.async.cg.shared.global [%0], [%1], 16;" \
        :: "r"(dst), "l"(src))
#define CP_COMMIT() asm volatile("cp.async.commit_group;")
#define CP_WAIT(n)  asm volatile("cp.async.wait_group %0;" :: "n"(n))

// ---------------------------------------------------------------------------
// Pre/post kernels
// ---------------------------------------------------------------------------
__global__ __launch_bounds__(256) void cvt16_kernel(
    const float* __restrict__ src, __half* __restrict__ dst, int n4)
{
    int i = blockIdx.x * blockDim.x + threadIdx.x;
    if (i >= n4) return;
    float4 v = ((const float4*)src)[i];
    uint2 u;
    u.x = cvt_h2(v.x, v.y);
    u.y = cvt_h2(v.z, v.w);
    ((uint2*)dst)[i] = u;
}

// Fused RMSNorm + RoPE. Q and K -> single fp16.
__global__ __launch_bounds__(256) void normrope_split_kernel(
    const float* __restrict__ qkv,
    const float* __restrict__ qw, const float* __restrict__ kw,
    const int* __restrict__ positions,
    __half* __restrict__ q_g, __half* __restrict__ k_g, int T)
{
    const int warp = (blockIdx.x * blockDim.x + threadIdx.x) >> 5;
    const int lane = threadIdx.x & 31;
    if (warp >= T * 24) return;
    const int t = warp / 24;
    const int h = warp % 24;

    const float* x = qkv + (size_t)t * QKV_COLS + h * HEAD_DIM;
    const float* nw = (h < 16) ? qw : kw;

    float v0 = x[lane], v1 = x[lane + 32], v2 = x[lane + 64], v3 = x[lane + 96];
    float ss = v0 * v0 + v1 * v1 + v2 * v2 + v3 * v3;
    #pragma unroll
    for (int o = 16; o; o >>= 1) ss += __shfl_xor_sync(0xffffffffu, ss, o);
    const float rn = rsqrtf(ss * (1.0f / HEAD_DIM) + RMS_EPS);

    float n0 = v0 * rn * nw[lane];
    float n1 = v1 * rn * nw[lane + 32];
    float n2 = v2 * rn * nw[lane + 64];
    float n3 = v3 * rn * nw[lane + 96];

    const double pos = (double)positions[t];
    const double LOG_THETA = 13.815510557964274;
    double f0 = exp(-((double)(2 * lane) / 128.0) * LOG_THETA);
    double f1 = exp(-((double)(2 * (lane + 32)) / 128.0) * LOG_THETA);
    double s0d, c0d, s1d, c1d;
    sincos(pos * f0, &s0d, &c0d);
    sincos(pos * f1, &s1d, &c1d);
    float c0 = (float)c0d, s0 = (float)s0d, c1 = (float)c1d, s1 = (float)s1d;

    float r0 = n0 * c0 - n2 * s0;
    float r2 = n2 * c0 + n0 * s0;
    float r1 = n1 * c1 - n3 * s1;
    float r3 = n3 * c1 + n1 * s1;

    __half* dst;
    size_t base;
    if (h < 16) {
        base = (size_t)t * Q_SIZE + h * HEAD_DIM;
        dst = q_g;
    } else {
        base = (size_t)(h - 16) * T * HEAD_DIM + (size_t)t * HEAD_DIM;
        dst = k_g;
    }
    dst[base + lane]      = __float2half_rn(r0);
    dst[base + lane + 32] = __float2half_rn(r1);
    dst[base + lane + 64] = __float2half_rn(r2);
    dst[base + lane + 96] = __float2half_rn(r3);
}

__global__ void vtrans_kernel(
    const float* __restrict__ qkv, __half* __restrict__ vh, int T)
{
    __shared__ float tile[32][33];
    const int kvh = blockIdx.z;
    const int d0 = blockIdx.y * 32;
    const int t0 = blockIdx.x * 32;
    for (int j = threadIdx.y; j < 32; j += 8) {
        tile[j][threadIdx.x] = qkv[(size_t)(t0 + j) * QKV_COLS + Q_SIZE + KV_SIZE
                                   + kvh * HEAD_DIM + d0 + threadIdx.x];
    }
    __syncthreads();
    for (int j = threadIdx.y; j < 32; j += 8) {
        float v = tile[threadIdx.x][j];
        size_t o = (size_t)kvh * HEAD_DIM * T + (size_t)(d0 + j) * T + t0 + threadIdx.x;
        vh[o] = __float2half_rn(v);
    }
}

// ---------------------------------------------------------------------------
// fp16 HMMA GEMM, single combo: C[M,N] = A[M,K] * B[N,K]^T (all fp16)
// BM=BN=128, BK=32, 256 threads, cp.async double-buffered, 2 CTAs/SM.
// ---------------------------------------------------------------------------
#define XBM 128
#define XBN 128
#define XBK 32
#define XSTR 40
#define STAGE_E (XBM * XSTR)
#define GEMM_SMEM (4 * STAGE_E * 2)   // 40960 bytes (2 stages x 2 buffers)

__global__ __launch_bounds__(256, 2) void gemm_f16(
    const __half* __restrict__ A, const __half* __restrict__ B,
    float* __restrict__ C, int M, int N, int K)
{
    extern __shared__ __half smg[];
    const uint32_t smb = smem_to_u32(smg);

    const int tid  = threadIdx.x;
    const int lane = tid & 31;
    const int wid  = tid >> 5;
    const int gid  = lane >> 2;
    const int tq   = lane & 3;
    const int wm   = (wid & 3) * 32;
    const int wn   = (wid >> 2) * 64;

    const int arow  = lane & 15;
    const int acol8 = (lane >> 4) << 3;
    const int brow  = ((lane >> 4) << 3) + (lane & 7);
    const int bcol8 = ((lane >> 3) & 1) << 3;

    const int bm = blockIdx.y * XBM;
    const int bn = blockIdx.x * XBN;

    #define G_ISSUE(stage, k0) do { \
        uint32_t sb0 = smb + (uint32_t)(stage) * 2 * STAGE_E * 2; \
        _Pragma("unroll") \
        for (int j = 0; j < 2; j++) { \
            int id = tid + j * 256; \
            int r = id >> 2, c = (id & 3) * 8; \
            size_t aoff = (size_t)(bm + r) * K + (k0) + c; \
            size_t boff = (size_t)(bn + r) * K + (k0) + c; \
            uint32_t doff = (uint32_t)(r * XSTR + c) * 2; \
            CP_ASYNC16(sb0 + doff, A + aoff); \
            CP_ASYNC16(sb0 + STAGE_E * 2 + doff, B + boff); \
        } \
    } while (0)

    float acc[2][8][4] = {};

    G_ISSUE(0, 0);
    CP_COMMIT();

    int stage = 0;
    for (int k0 = 0; k0 < K; k0 += XBK, stage ^= 1) {
        if (k0 + XBK < K) {
            G_ISSUE(stage ^ 1, k0 + XBK);
            CP_COMMIT();
            CP_WAIT(1);
        } else {
            CP_WAIT(0);
        }
        __syncthreads();

        const uint32_t sA = smb + (uint32_t)stage * 2 * STAGE_E * 2;
        const uint32_t sB = sA + STAGE_E * 2;

        #pragma unroll
        for (int kk = 0; kk < XBK; kk += 16) {
            uint32_t a[2][4];
            #pragma unroll
            for (int mt = 0; mt < 2; mt++) {
                uint32_t aoff = (uint32_t)((wm + mt * 16 + arow) * XSTR + kk + acol8) * 2;
                LDSM_X4(a[mt][0], a[mt][1], a[mt][2], a[mt][3], sA + aoff);
            }
            #pragma unroll
            for (int p = 0; p < 4; p++) {
                uint32_t boff = (uint32_t)((wn + p * 16 + brow) * XSTR + kk + bcol8) * 2;
                uint32_t b0, b1, b2, b3;
                LDSM_X4(b0, b1, b2, b3, sB + boff);
                #pragma unroll
                for (int mt = 0; mt < 2; mt++) {
                    mma_f16(acc[mt][2 * p], a[mt], b0, b1);
                    mma_f16(acc[mt][2 * p + 1], a[mt], b2, b3);
                }
            }
        }
        __syncthreads();
    }

    #pragma unroll
    for (int mt = 0; mt < 2; mt++) {
        int row = bm + wm + mt * 16 + gid;
        #pragma unroll
        for (int nt = 0; nt < 8; nt++) {
            int col = bn + wn + nt * 8 + tq * 2;
            *(float2*)&C[(size_t)row * N + col] =
                make_float2(acc[mt][nt][0], acc[mt][nt][1]);
            *(float2*)&C[(size_t)(row + 8) * N + col] =
                make_float2(acc[mt][nt][2], acc[mt][nt][3]);
        }
    }
}

// ---------------------------------------------------------------------------
// fp16 HMMA flash attention — q block 64, kv tile 64, 128 threads
// (4 warps x 16 rows), 3 CTAs/SM. QK 1 combo; PV 1 combo. Persistent Q
// fragments; Q staged through K0|K1 region. Double-buffered, 1 sync/iter.
// (unchanged from R14)
// ---------------------------------------------------------------------------
#define AQB 64
#define AKB 64
#define SSTR 136
#define VSTR 72
#define KT_B (AKB * SSTR * 2)           // 17408 B
#define VT_B (HEAD_DIM * VSTR * 2)      // 18432 B
#define OFF_K(s)  ((uint32_t)(s) * KT_B)
#define OFF_V(s)  (2u * KT_B + (uint32_t)(s) * VT_B)
#define ATT_SMEM  (2 * KT_B + 2 * VT_B) // 71680 B

__global__ __launch_bounds__(128, 3) void attn_mma(
    const __half* __restrict__ q_g, const __half* __restrict__ k_g,
    const __half* __restrict__ v_g,
    __half* __restrict__ attn_out, int T)
{
    extern __shared__ char sm[];
    const uint32_t smb = smem_to_u32(sm);
    const int tid  = threadIdx.x;
    const int lane = tid & 31;
    const int wid  = tid >> 5;
    const int gid  = lane >> 2;
    const int tq   = lane & 3;

    const int qb   = (gridDim.x - 1) - blockIdx.x;
    const int head = blockIdx.y;
    const int kvh  = head >> 1;
    const int q0   = qb * AQB;
    const int wrow = wid * 16;
    const int iters = qb + 1;

    const int arow  = lane & 15;
    const int acol8 = (lane >> 4) << 3;
    const int brow  = ((lane >> 4) << 3) + (lane & 7);
    const int bcol8 = ((lane >> 3) & 1) << 3;

    const size_t kbase = (size_t)kvh * T * HEAD_DIM;
    const size_t vbase = (size_t)kvh * HEAD_DIM * T;

    #define ATT_PREFETCH(itn) do { \
        const int st_ = (itn) & 1; \
        const uint32_t kb_ = smb + OFF_K(st_); \
        const uint32_t vb_ = smb + OFF_V(st_); \
        const size_t ko_ = kbase + (size_t)(itn) * AKB * HEAD_DIM; \
        const size_t vo_ = vbase + (size_t)(itn) * AKB; \
        _Pragma("unroll") \
        for (int j = 0; j < 8; j++) { \
            int i = tid + j * 128; \
            int r_ = i >> 4, c_ = (i & 15) << 3; \
            uint32_t doff_ = (uint32_t)(r_ * SSTR + c_) * 2; \
            CP_ASYNC16(kb_ + doff_, k_g + ko_ + (size_t)r_ * HEAD_DIM + c_); \
            int d_ = i >> 3, vc_ = (i & 7) << 3; \
            uint32_t vdoff_ = (uint32_t)(d_ * VSTR + vc_) * 2; \
            CP_ASYNC16(vb_ + vdoff_, v_g + vo_ + (size_t)d_ * T + vc_); \
        } \
        CP_COMMIT(); \
    } while (0)

    // Prologue: stage Q through K0|K1, build frags, then prefetch tile 0.
    for (int i = tid; i < 512; i += 128) {
        int r = i >> 3, c = (i & 7) << 4;
        uint32_t doff = (uint32_t)(r * SSTR + c) * 2;
        size_t o = (size_t)(q0 + r) * Q_SIZE + head * HEAD_DIM + c;
        *(uint4*)(sm + doff)      = *(const uint4*)&q_g[o];
        *(uint4*)(sm + doff + 16) = *(const uint4*)&q_g[o + 8];
    }
    __syncthreads();

    uint32_t qh[8][4];
    #pragma unroll
    for (int kt = 0; kt < 8; kt++) {
        uint32_t aoff = (uint32_t)((wrow + arow) * SSTR + kt * 16 + acol8) * 2;
        LDSM_X4(qh[kt][0], qh[kt][1], qh[kt][2], qh[kt][3], smb + aoff);
    }
    __syncthreads();

    ATT_PREFETCH(0);

    const int grow0 = q0 + wrow + gid;
    const int grow1 = grow0 + 8;

    float m0 = -1e30f, m1 = -1e30f, l0s = 0.0f, l1s = 0.0f;
    float o[16][4] = {};

    for (int it = 0; it < iters; it++) {
        const int k0 = it * AKB;
        const int st = it & 1;
        const uint32_t k_b = smb + OFF_K(st);
        const uint32_t v_b = smb + OFF_V(st);

        CP_WAIT(0);
        __syncthreads();

        if (it + 1 < iters) ATT_PREFETCH(it + 1);

        // S = Q K^T
        float s[8][4];
        #pragma unroll
        for (int nt = 0; nt < 8; nt++)
            #pragma unroll
            for (int c = 0; c < 4; c++) s[nt][c] = 0.0f;

        #pragma unroll
        for (int kt = 0; kt < 8; kt++) {
            #pragma unroll
            for (int p = 0; p < 4; p++) {
                uint32_t boff = (uint32_t)((p * 16 + brow) * SSTR + kt * 16 + bcol8) * 2;
                uint32_t b0, b1, b2, b3;
                LDSM_X4(b0, b1, b2, b3, k_b + boff);
                mma_f16(s[2 * p], qh[kt], b0, b1);
                mma_f16(s[2 * p + 1], qh[kt], b2, b3);
            }
        }

        // softmax (log2-domain)
        const bool diag = (it == qb);
        float mx0 = m0, mx1 = m1;
        #pragma unroll
        for (int nt = 0; nt < 8; nt++) {
            int colb = k0 + nt * 8 + tq * 2;
            #pragma unroll
            for (int c = 0; c < 2; c++) {
                float v0 = s[nt][c] * SCALE_L2E;
                float v1 = s[nt][c + 2] * SCALE_L2E;
                if (diag && (colb + c > grow0)) v0 = -1e30f;
                if (diag && (colb + c > grow1)) v1 = -1e30f;
                s[nt][c] = v0; s[nt][c + 2] = v1;
                mx0 = fmaxf(mx0, v0); mx1 = fmaxf(mx1, v1);
            }
        }
        mx0 = fmaxf(mx0, __shfl_xor_sync(0xffffffffu, mx0, 1));
        mx0 = fmaxf(mx0, __shfl_xor_sync(0xffffffffu, mx0, 2));
        mx1 = fmaxf(mx1, __shfl_xor_sync(0xffffffffu, mx1, 1));
        mx1 = fmaxf(mx1, __shfl_xor_sync(0xffffffffu, mx1, 2));

        const float a0 = ex2f(m0 - mx0);
        const float a1 = ex2f(m1 - mx1);
        m0 = mx0; m1 = mx1;

        float sum0 = 0.0f, sum1 = 0.0f;
        #pragma unroll
        for (int nt = 0; nt < 8; nt++) {
            #pragma unroll
            for (int c = 0; c < 2; c++) {
                float p0 = ex2f(s[nt][c] - m0);
                float p1 = ex2f(s[nt][c + 2] - m1);
                s[nt][c] = p0; s[nt][c + 2] = p1;
                sum0 += p0; sum1 += p1;
            }
        }
        sum0 += __shfl_xor_sync(0xffffffffu, sum0, 1);
        sum0 += __shfl_xor_sync(0xffffffffu, sum0, 2);
        sum1 += __shfl_xor_sync(0xffffffffu, sum1, 1);
        sum1 += __shfl_xor_sync(0xffffffffu, sum1, 2);
        l0s = l0s * a0 + sum0;
        l1s = l1s * a1 + sum1;

        #pragma unroll
        for (int nt = 0; nt < 16; nt++) {
            o[nt][0] *= a0; o[nt][1] *= a0;
            o[nt][2] *= a1; o[nt][3] *= a1;
        }

        // O += P @ V
        #pragma unroll
        for (int kt = 0; kt < 4; kt++) {
            uint32_t ph[4];
            ph[0] = cvt_h2(s[2 * kt][0], s[2 * kt][1]);
            ph[1] = cvt_h2(s[2 * kt][2], s[2 * kt][3]);
            ph[2] = cvt_h2(s[2 * kt + 1][0], s[2 * kt + 1][1]);
            ph[3] = cvt_h2(s[2 * kt + 1][2], s[2 * kt + 1][3]);
            #pragma unroll
            for (int p = 0; p < 8; p++) {
                uint32_t boff = (uint32_t)((p * 16 + brow) * VSTR + kt * 16 + bcol8) * 2;
                uint32_t v0r, v1r, v2r, v3r;
                LDSM_X4(v0r, v1r, v2r, v3r, v_b + boff);
                mma_f16(o[2 * p], ph, v0r, v1r);
                mma_f16(o[2 * p + 1], ph, v2r, v3r);
            }
        }
    }

    // Epilogue
    const float inv0 = 1.0f / l0s;
    const float inv1 = 1.0f / l1s;
    #pragma unroll
    for (int nt = 0; nt < 16; nt++) {
        int dcol = head * HEAD_DIM + nt * 8 + tq * 2;
        *(uint32_t*)&attn_out[(size_t)grow0 * Q_SIZE + dcol] =
            cvt_h2(o[nt][0] * inv0, o[nt][1] * inv0);
        *(uint32_t*)&attn_out[(size_t)grow1 * Q_SIZE + dcol] =
            cvt_h2(o[nt][2] * inv1, o[nt][3] * inv1);
    }
}

// ---------------------------------------------------------------------------
// Launch
// ---------------------------------------------------------------------------
extern "C" void kernel_launch(void* const* d_in, const int* in_sizes, int n_in,
                              void* d_out, int out_size)
{
    const float* hidden = (const float*)d_in[0];
    const float* qkv_w  = (const float*)d_in[1];
    const float* q_nw   = (const float*)d_in[2];
    const float* k_nw   = (const float*)d_in[3];
    const float* o_w    = (const float*)d_in[4];
    const int*   pos    = (const int*)d_in[5];
    float* out = (float*)d_out;

    const int T = in_sizes[0] / HIDDEN;

    float* qkv;  cudaGetSymbolAddress((void**)&qkv,  g_qkv);
    __half *hid, *w1, *w2, *at, *q, *k, *v;
    cudaGetSymbolAddress((void**)&hid, g_hid);
    cudaGetSymbolAddress((void**)&w1,  g_w1);
    cudaGetSymbolAddress((void**)&w2,  g_w2);
    cudaGetSymbolAddress((void**)&at,  g_at);
    cudaGetSymbolAddress((void**)&q,   g_q);
    cudaGetSymbolAddress((void**)&k,   g_k);
    cudaGetSymbolAddress((void**)&v,   g_v);

    cudaFuncSetAttribute(attn_mma, cudaFuncAttributeMaxDynamicSharedMemorySize,
                         ATT_SMEM);
    cudaFuncSetAttribute(gemm_f16, cudaFuncAttributeMaxDynamicSharedMemorySize,
                         GEMM_SMEM);

    // 0) Convert inputs to fp16
    {
        int n4 = T * HIDDEN / 4;
        cvt16_kernel<<<(n4 + 255) / 256, 256>>>(hidden, hid, n4);
        n4 = QKV_COLS * HIDDEN / 4;
        cvt16_kernel<<<(n4 + 255) / 256, 256>>>(qkv_w, w1, n4);
        n4 = HIDDEN * Q_SIZE / 4;
        cvt16_kernel<<<(n4 + 255) / 256, 256>>>(o_w, w2, n4);
    }
    // 1) QKV projection (single-combo fp16 GEMM)
    {
        dim3 grid(QKV_COLS / XBN, T / XBM);
        gemm_f16<<<grid, 256, GEMM_SMEM>>>(hid, w1, qkv, T, QKV_COLS, HIDDEN);
    }
    // 2) Fused RMSNorm + RoPE (Q, K single fp16); transpose V
    {
        int warps = T * 24;
        int blocks = (warps + 7) / 8;
        normrope_split_kernel<<<blocks, 256>>>(qkv, q_nw, k_nw, pos, q, k, T);
        dim3 vg(T / 32, HEAD_DIM / 32, NUM_KV);
        vtrans_kernel<<<vg, dim3(32, 8)>>>(qkv, v, T);
    }
    // 3) Attention (q64 x kv64, 3 CTAs/SM, 1-combo QK/PV)
    {
        dim3 grid(T / AQB, NUM_HEADS);
        attn_mma<<<grid, 128, ATT_SMEM>>>(q, k, v, at, T);
    }
    // 4) Output projection (single-combo fp16 GEMM)
    {
        dim3 grid(HIDDEN / XBN, T / XBM);
        gemm_f16<<<grid, 256, GEMM_SMEM>>>(at, w2, out, T, HIDDEN, HIDDEN);
    }
}

// round 16
// speedup vs baseline: 2.3592x; 1.7705x over previous
#include <cuda_runtime.h>
#include <cuda_bf16.h>
#include <cuda_fp16.h>
#include <math.h>
#include <float.h>
#include <cstdint>

// Problem constants
#define HIDDEN    2048
#define NUM_HEADS 16
#define NUM_KV    8
#define HEAD_DIM  128
#define Q_SIZE    (NUM_HEADS * HEAD_DIM)        // 2048
#define KV_SIZE   (NUM_KV * HEAD_DIM)           // 1024
#define QKV_COLS  (Q_SIZE + 2 * KV_SIZE)        // 4096
#define SCALE     0.08838834764831845f          // 128^-0.5
#define SCALE_L2E 0.12751985675839602f          // SCALE * log2(e)
#define RMS_EPS   1e-6f

#define MAX_T 4096

// Scratch (static device globals)
__device__ float g_qkv[(size_t)MAX_T * QKV_COLS];
__device__ __half g_hid[(size_t)MAX_T * HIDDEN];
__device__ __half g_w1[(size_t)QKV_COLS * HIDDEN];
__device__ __half g_w2[(size_t)HIDDEN * Q_SIZE];
__device__ __half g_at[(size_t)MAX_T * Q_SIZE];
__device__ __half g_q[(size_t)MAX_T * Q_SIZE];
__device__ __half g_k[(size_t)NUM_KV * MAX_T * HEAD_DIM];
__device__ __half g_v[(size_t)NUM_KV * HEAD_DIM * MAX_T];   // [kvh][d][t]
__device__ float2 g_rope[(size_t)MAX_T * 64];               // (t, j): cos, sin

// ===========================================================================
// Helpers
// ===========================================================================
__device__ __forceinline__ uint32_t smem_to_u32(const void* p) {
    uint32_t a;
    asm("{ .reg .u64 t; cvta.to.shared.u64 t, %1; cvt.u32.u64 %0, t; }"
        : "=r"(a) : "l"(p));
    return a;
}
__device__ __forceinline__ float ex2f(float x) {
    float r;
    asm("ex2.approx.f32 %0, %1;" : "=f"(r) : "f"(x));
    return r;
}
__device__ __forceinline__ uint32_t cvt_h2(float a, float b) {
    uint32_t r;
    asm("cvt.rn.f16x2.f32 %0, %1, %2;" : "=r"(r) : "f"(b), "f"(a));
    return r;
}

__device__ __forceinline__ void mma_f16(float* d, const uint32_t* a,
                                        uint32_t b0, uint32_t b1) {
    asm volatile(
        "mma.sync.aligned.m16n8k16.row.col.f32.f16.f16.f32 "
        "{%0,%1,%2,%3}, {%4,%5,%6,%7}, {%8,%9}, {%0,%1,%2,%3};"
        : "+f"(d[0]), "+f"(d[1]), "+f"(d[2]), "+f"(d[3])
        : "r"(a[0]), "r"(a[1]), "r"(a[2]), "r"(a[3]), "r"(b0), "r"(b1));
}

#define LDSM_X4(r0, r1, r2, r3, addr) \
    asm volatile("ldmatrix.sync.aligned.m8n8.x4.shared.b16 {%0,%1,%2,%3}, [%4];" \
        : "=r"(r0), "=r"(r1), "=r"(r2), "=r"(r3) : "r"(addr))

#define CP_ASYNC16(dst, src) \
    asm volatile("cp.async.cg.shared.global [%0], [%1], 16;" \
        :: "r"(dst), "l"(src))
#define CP_COMMIT() asm volatile("cp.async.commit_group;")
#define CP_WAIT(n)  asm volatile("cp.async.wait_group %0;" :: "n"(n))

// ---------------------------------------------------------------------------
// Pre/post kernels
// ---------------------------------------------------------------------------
__global__ __launch_bounds__(256) void cvt16_kernel(
    const float* __restrict__ src, __half* __restrict__ dst, int n4)
{
    int i = blockIdx.x * blockDim.x + threadIdx.x;
    if (i >= n4) return;
    float4 v = ((const float4*)src)[i];
    uint2 u;
    u.x = cvt_h2(v.x, v.y);
    u.y = cvt_h2(v.z, v.w);
    ((uint2*)dst)[i] = u;
}

// RoPE cos/sin table: one double-precision sincos per (t, j). Tiny kernel;
// removes all fp64 from the hot normrope pass. Values bit-identical to R15.
__global__ __launch_bounds__(256) void rope_table_kernel(
    const int* __restrict__ positions, float2* __restrict__ tab, int T)
{
    int i = blockIdx.x * blockDim.x + threadIdx.x;
    if (i >= T * 64) return;
    int t = i >> 6, j = i & 63;
    const double LOG_THETA = 13.815510557964274;   // ln(1e6)
    double pos = (double)positions[t];
    double f = exp(-((double)(2 * j) / 128.0) * LOG_THETA);
    double s, c;
    sincos(pos * f, &s, &c);
    tab[i] = make_float2((float)c, (float)s);
}

// Fused RMSNorm + RoPE (pure fp32; angles from table). Q,K -> single fp16.
__global__ __launch_bounds__(256) void normrope_split_kernel(
    const float* __restrict__ qkv,
    const float* __restrict__ qw, const float* __restrict__ kw,
    const float2* __restrict__ rope,
    __half* __restrict__ q_g, __half* __restrict__ k_g, int T)
{
    const int warp = (blockIdx.x * blockDim.x + threadIdx.x) >> 5;
    const int lane = threadIdx.x & 31;
    if (warp >= T * 24) return;
    const int t = warp / 24;
    const int h = warp % 24;

    const float* x = qkv + (size_t)t * QKV_COLS + h * HEAD_DIM;
    const float* nw = (h < 16) ? qw : kw;

    float v0 = x[lane], v1 = x[lane + 32], v2 = x[lane + 64], v3 = x[lane + 96];
    float ss = v0 * v0 + v1 * v1 + v2 * v2 + v3 * v3;
    #pragma unroll
    for (int o = 16; o; o >>= 1) ss += __shfl_xor_sync(0xffffffffu, ss, o);
    const float rn = rsqrtf(ss * (1.0f / HEAD_DIM) + RMS_EPS);

    float n0 = v0 * rn * nw[lane];
    float n1 = v1 * rn * nw[lane + 32];
    float n2 = v2 * rn * nw[lane + 64];
    float n3 = v3 * rn * nw[lane + 96];

    float2 cs0 = rope[(size_t)t * 64 + lane];        // j = lane
    float2 cs1 = rope[(size_t)t * 64 + lane + 32];   // j = lane + 32
    float c0 = cs0.x, s0 = cs0.y, c1 = cs1.x, s1 = cs1.y;

    float r0 = n0 * c0 - n2 * s0;
    float r2 = n2 * c0 + n0 * s0;
    float r1 = n1 * c1 - n3 * s1;
    float r3 = n3 * c1 + n1 * s1;

    __half* dst;
    size_t base;
    if (h < 16) {
        base = (size_t)t * Q_SIZE + h * HEAD_DIM;
        dst = q_g;
    } else {
        base = (size_t)(h - 16) * T * HEAD_DIM + (size_t)t * HEAD_DIM;
        dst = k_g;
    }
    dst[base + lane]      = __float2half_rn(r0);
    dst[base + lane + 32] = __float2half_rn(r1);
    dst[base + lane + 64] = __float2half_rn(r2);
    dst[base + lane + 96] = __float2half_rn(r3);
}

__global__ void vtrans_kernel(
    const float* __restrict__ qkv, __half* __restrict__ vh, int T)
{
    __shared__ float tile[32][33];
    const int kvh = blockIdx.z;
    const int d0 = blockIdx.y * 32;
    const int t0 = blockIdx.x * 32;
    for (int j = threadIdx.y; j < 32; j += 8) {
        tile[j][threadIdx.x] = qkv[(size_t)(t0 + j) * QKV_COLS + Q_SIZE + KV_SIZE
                                   + kvh * HEAD_DIM + d0 + threadIdx.x];
    }
    __syncthreads();
    for (int j = threadIdx.y; j < 32; j += 8) {
        float v = tile[threadIdx.x][j];
        size_t o = (size_t)kvh * HEAD_DIM * T + (size_t)(d0 + j) * T + t0 + threadIdx.x;
        vh[o] = __float2half_rn(v);
    }
}

// ---------------------------------------------------------------------------
// fp16 HMMA GEMM, single combo, BK=64: C[M,N] = A[M,K] * B[N,K]^T
// BM=BN=128, BK=64, 256 threads, cp.async double-buffered, 2 CTAs/SM.
// ---------------------------------------------------------------------------
#define XBM 128
#define XBN 128
#define XBK 64
#define XSTR 72                        // 64 + 8 pad (bf16 elems)
#define STAGE_E (XBM * XSTR)           // 9216 elems per buffer
#define GEMM_SMEM (4 * STAGE_E * 2)    // 73728 bytes (2 stages x 2 buffers)

__global__ __launch_bounds__(256, 2) void gemm_f16(
    const __half* __restrict__ A, const __half* __restrict__ B,
    float* __restrict__ C, int M, int N, int K)
{
    extern __shared__ __half smg[];
    const uint32_t smb = smem_to_u32(smg);

    const int tid  = threadIdx.x;
    const int lane = tid & 31;
    const int wid  = tid >> 5;
    const int gid  = lane >> 2;
    const int tq   = lane & 3;
    const int wm   = (wid & 3) * 32;
    const int wn   = (wid >> 2) * 64;

    const int arow  = lane & 15;
    const int acol8 = (lane >> 4) << 3;
    const int brow  = ((lane >> 4) << 3) + (lane & 7);
    const int bcol8 = ((lane >> 3) & 1) << 3;

    const int bm = blockIdx.y * XBM;
    const int bn = blockIdx.x * XBN;

    // 128 rows x 64 cols per buffer = 1024 uint4; 256 threads x 4 chunks
    #define G_ISSUE(stage, k0) do { \
        uint32_t sb0 = smb + (uint32_t)(stage) * 2 * STAGE_E * 2; \
        _Pragma("unroll") \
        for (int j = 0; j < 4; j++) { \
            int id = tid + j * 256; \
            int r = id >> 3, c = (id & 7) * 8; \
            size_t aoff = (size_t)(bm + r) * K + (k0) + c; \
            size_t boff = (size_t)(bn + r) * K + (k0) + c; \
            uint32_t doff = (uint32_t)(r * XSTR + c) * 2; \
            CP_ASYNC16(sb0 + doff, A + aoff); \
            CP_ASYNC16(sb0 + STAGE_E * 2 + doff, B + boff); \
        } \
    } while (0)

    float acc[2][8][4] = {};

    G_ISSUE(0, 0);
    CP_COMMIT();

    int stage = 0;
    for (int k0 = 0; k0 < K; k0 += XBK, stage ^= 1) {
        if (k0 + XBK < K) {
            G_ISSUE(stage ^ 1, k0 + XBK);
            CP_COMMIT();
            CP_WAIT(1);
        } else {
            CP_WAIT(0);
        }
        __syncthreads();

        const uint32_t sA = smb + (uint32_t)stage * 2 * STAGE_E * 2;
        const uint32_t sB = sA + STAGE_E * 2;

        #pragma unroll
        for (int kk = 0; kk < XBK; kk += 16) {
            uint32_t a[2][4];
            #pragma unroll
            for (int mt = 0; mt < 2; mt++) {
                uint32_t aoff = (uint32_t)((wm + mt * 16 + arow) * XSTR + kk + acol8) * 2;
                LDSM_X4(a[mt][0], a[mt][1], a[mt][2], a[mt][3], sA + aoff);
            }
            #pragma unroll
            for (int p = 0; p < 4; p++) {
                uint32_t boff = (uint32_t)((wn + p * 16 + brow) * XSTR + kk + bcol8) * 2;
                uint32_t b0, b1, b2, b3;
                LDSM_X4(b0, b1, b2, b3, sB + boff);
                #pragma unroll
                for (int mt = 0; mt < 2; mt++) {
                    mma_f16(acc[mt][2 * p], a[mt], b0, b1);
                    mma_f16(acc[mt][2 * p + 1], a[mt], b2, b3);
                }
            }
        }
        __syncthreads();
    }

    #pragma unroll
    for (int mt = 0; mt < 2; mt++) {
        int row = bm + wm + mt * 16 + gid;
        #pragma unroll
        for (int nt = 0; nt < 8; nt++) {
            int col = bn + wn + nt * 8 + tq * 2;
            *(float2*)&C[(size_t)row * N + col] =
                make_float2(acc[mt][nt][0], acc[mt][nt][1]);
            *(float2*)&C[(size_t)(row + 8) * N + col] =
                make_float2(acc[mt][nt][2], acc[mt][nt][3]);
        }
    }
}

// ---------------------------------------------------------------------------
// fp16 HMMA flash attention — UNCHANGED champion (q64 x kv64, 128 threads,
// 3 CTAs/SM, 1-combo QK/PV, persistent Q frags, double-buffered, 1 sync/iter)
// ---------------------------------------------------------------------------
#define AQB 64
#define AKB 64
#define SSTR 136
#define VSTR 72
#define KT_B (AKB * SSTR * 2)           // 17408 B
#define VT_B (HEAD_DIM * VSTR * 2)      // 18432 B
#define OFF_K(s)  ((uint32_t)(s) * KT_B)
#define OFF_V(s)  (2u * KT_B + (uint32_t)(s) * VT_B)
#define ATT_SMEM  (2 * KT_B + 2 * VT_B) // 71680 B

__global__ __launch_bounds__(128, 3) void attn_mma(
    const __half* __restrict__ q_g, const __half* __restrict__ k_g,
    const __half* __restrict__ v_g,
    __half* __restrict__ attn_out, int T)
{
    extern __shared__ char sm[];
    const uint32_t smb = smem_to_u32(sm);
    const int tid  = threadIdx.x;
    const int lane = tid & 31;
    const int wid  = tid >> 5;
    const int gid  = lane >> 2;
    const int tq   = lane & 3;

    const int qb   = (gridDim.x - 1) - blockIdx.x;
    const int head = blockIdx.y;
    const int kvh  = head >> 1;
    const int q0   = qb * AQB;
    const int wrow = wid * 16;
    const int iters = qb + 1;

    const int arow  = lane & 15;
    const int acol8 = (lane >> 4) << 3;
    const int brow  = ((lane >> 4) << 3) + (lane & 7);
    const int bcol8 = ((lane >> 3) & 1) << 3;

    const size_t kbase = (size_t)kvh * T * HEAD_DIM;
    const size_t vbase = (size_t)kvh * HEAD_DIM * T;

    #define ATT_PREFETCH(itn) do { \
        const int st_ = (itn) & 1; \
        const uint32_t kb_ = smb + OFF_K(st_); \
        const uint32_t vb_ = smb + OFF_V(st_); \
        const size_t ko_ = kbase + (size_t)(itn) * AKB * HEAD_DIM; \
        const size_t vo_ = vbase + (size_t)(itn) * AKB; \
        _Pragma("unroll") \
        for (int j = 0; j < 8; j++) { \
            int i = tid + j * 128; \
            int r_ = i >> 4, c_ = (i & 15) << 3; \
            uint32_t doff_ = (uint32_t)(r_ * SSTR + c_) * 2; \
            CP_ASYNC16(kb_ + doff_, k_g + ko_ + (size_t)r_ * HEAD_DIM + c_); \
            int d_ = i >> 3, vc_ = (i & 7) << 3; \
            uint32_t vdoff_ = (uint32_t)(d_ * VSTR + vc_) * 2; \
            CP_ASYNC16(vb_ + vdoff_, v_g + vo_ + (size_t)d_ * T + vc_); \
        } \
        CP_COMMIT(); \
    } while (0)

    for (int i = tid; i < 512; i += 128) {
        int r = i >> 3, c = (i & 7) << 4;
        uint32_t doff = (uint32_t)(r * SSTR + c) * 2;
        size_t o = (size_t)(q0 + r) * Q_SIZE + head * HEAD_DIM + c;
        *(uint4*)(sm + doff)      = *(const uint4*)&q_g[o];
        *(uint4*)(sm + doff + 16) = *(const uint4*)&q_g[o + 8];
    }
    __syncthreads();

    uint32_t qh[8][4];
    #pragma unroll
    for (int kt = 0; kt < 8; kt++) {
        uint32_t aoff = (uint32_t)((wrow + arow) * SSTR + kt * 16 + acol8) * 2;
        LDSM_X4(qh[kt][0], qh[kt][1], qh[kt][2], qh[kt][3], smb + aoff);
    }
    __syncthreads();

    ATT_PREFETCH(0);

    const int grow0 = q0 + wrow + gid;
    const int grow1 = grow0 + 8;

    float m0 = -1e30f, m1 = -1e30f, l0s = 0.0f, l1s = 0.0f;
    float o[16][4] = {};

    for (int it = 0; it < iters; it++) {
        const int k0 = it * AKB;
        const int st = it & 1;
        const uint32_t k_b = smb + OFF_K(st);
        const uint32_t v_b = smb + OFF_V(st);

        CP_WAIT(0);
        __syncthreads();

        if (it + 1 < iters) ATT_PREFETCH(it + 1);

        float s[8][4];
        #pragma unroll
        for (int nt = 0; nt < 8; nt++)
            #pragma unroll
            for (int c = 0; c < 4; c++) s[nt][c] = 0.0f;

        #pragma unroll
        for (int kt = 0; kt < 8; kt++) {
            #pragma unroll
            for (int p = 0; p < 4; p++) {
                uint32_t boff = (uint32_t)((p * 16 + brow) * SSTR + kt * 16 + bcol8) * 2;
                uint32_t b0, b1, b2, b3;
                LDSM_X4(b0, b1, b2, b3, k_b + boff);
                mma_f16(s[2 * p], qh[kt], b0, b1);
                mma_f16(s[2 * p + 1], qh[kt], b2, b3);
            }
        }

        const bool diag = (it == qb);
        float mx0 = m0, mx1 = m1;
        #pragma unroll
        for (int nt = 0; nt < 8; nt++) {
            int colb = k0 + nt * 8 + tq * 2;
            #pragma unroll
            for (int c = 0; c < 2; c++) {
                float v0 = s[nt][c] * SCALE_L2E;
                float v1 = s[nt][c + 2] * SCALE_L2E;
                if (diag && (colb + c > grow0)) v0 = -1e30f;
                if (diag && (colb + c > grow1)) v1 = -1e30f;
                s[nt][c] = v0; s[nt][c + 2] = v1;
                mx0 = fmaxf(mx0, v0); mx1 = fmaxf(mx1, v1);
            }
        }
        mx0 = fmaxf(mx0, __shfl_xor_sync(0xffffffffu, mx0, 1));
        mx0 = fmaxf(mx0, __shfl_xor_sync(0xffffffffu, mx0, 2));
        mx1 = fmaxf(mx1, __shfl_xor_sync(0xffffffffu, mx1, 1));
        mx1 = fmaxf(mx1, __shfl_xor_sync(0xffffffffu, mx1, 2));

        const float a0 = ex2f(m0 - mx0);
        const float a1 = ex2f(m1 - mx1);
        m0 = mx0; m1 = mx1;

        float sum0 = 0.0f, sum1 = 0.0f;
        #pragma unroll
        for (int nt = 0; nt < 8; nt++) {
            #pragma unroll
            for (int c = 0; c < 2; c++) {
                float p0 = ex2f(s[nt][c] - m0);
                float p1 = ex2f(s[nt][c + 2] - m1);
                s[nt][c] = p0; s[nt][c + 2] = p1;
                sum0 += p0; sum1 += p1;
            }
        }
        sum0 += __shfl_xor_sync(0xffffffffu, sum0, 1);
        sum0 += __shfl_xor_sync(0xffffffffu, sum0, 2);
        sum1 += __shfl_xor_sync(0xffffffffu, sum1, 1);
        sum1 += __shfl_xor_sync(0xffffffffu, sum1, 2);
        l0s = l0s * a0 + sum0;
        l1s = l1s * a1 + sum1;

        #pragma unroll
        for (int nt = 0; nt < 16; nt++) {
            o[nt][0] *= a0; o[nt][1] *= a0;
            o[nt][2] *= a1; o[nt][3] *= a1;
        }

        #pragma unroll
        for (int kt = 0; kt < 4; kt++) {
            uint32_t ph[4];
            ph[0] = cvt_h2(s[2 * kt][0], s[2 * kt][1]);
            ph[1] = cvt_h2(s[2 * kt][2], s[2 * kt][3]);
            ph[2] = cvt_h2(s[2 * kt + 1][0], s[2 * kt + 1][1]);
            ph[3] = cvt_h2(s[2 * kt + 1][2], s[2 * kt + 1][3]);
            #pragma unroll
            for (int p = 0; p < 8; p++) {
                uint32_t boff = (uint32_t)((p * 16 + brow) * VSTR + kt * 16 + bcol8) * 2;
                uint32_t v0r, v1r, v2r, v3r;
                LDSM_X4(v0r, v1r, v2r, v3r, v_b + boff);
                mma_f16(o[2 * p], ph, v0r, v1r);
                mma_f16(o[2 * p + 1], ph, v2r, v3r);
            }
        }
    }

    const float inv0 = 1.0f / l0s;
    const float inv1 = 1.0f / l1s;
    #pragma unroll
    for (int nt = 0; nt < 16; nt++) {
        int dcol = head * HEAD_DIM + nt * 8 + tq * 2;
        *(uint32_t*)&attn_out[(size_t)grow0 * Q_SIZE + dcol] =
            cvt_h2(o[nt][0] * inv0, o[nt][1] * inv0);
        *(uint32_t*)&attn_out[(size_t)grow1 * Q_SIZE + dcol] =
            cvt_h2(o[nt][2] * inv1, o[nt][3] * inv1);
    }
}

// ---------------------------------------------------------------------------
// Launch
// ---------------------------------------------------------------------------
extern "C" void kernel_launch(void* const* d_in, const int* in_sizes, int n_in,
                              void* d_out, int out_size)
{
    const float* hidden = (const float*)d_in[0];
    const float* qkv_w  = (const float*)d_in[1];
    const float* q_nw   = (const float*)d_in[2];
    const float* k_nw   = (const float*)d_in[3];
    const float* o_w    = (const float*)d_in[4];
    const int*   pos    = (const int*)d_in[5];
    float* out = (float*)d_out;

    const int T = in_sizes[0] / HIDDEN;

    float* qkv;  cudaGetSymbolAddress((void**)&qkv,  g_qkv);
    __half *hid, *w1, *w2, *at, *q, *k, *v;
    float2* rope;
    cudaGetSymbolAddress((void**)&hid,  g_hid);
    cudaGetSymbolAddress((void**)&w1,   g_w1);
    cudaGetSymbolAddress((void**)&w2,   g_w2);
    cudaGetSymbolAddress((void**)&at,   g_at);
    cudaGetSymbolAddress((void**)&q,    g_q);
    cudaGetSymbolAddress((void**)&k,    g_k);
    cudaGetSymbolAddress((void**)&v,    g_v);
    cudaGetSymbolAddress((void**)&rope, g_rope);

    cudaFuncSetAttribute(attn_mma, cudaFuncAttributeMaxDynamicSharedMemorySize,
                         ATT_SMEM);
    cudaFuncSetAttribute(gemm_f16, cudaFuncAttributeMaxDynamicSharedMemorySize,
                         GEMM_SMEM);

    // 0) Convert inputs to fp16 + build RoPE table (overlappable small kernels)
    {
        int n4 = T * HIDDEN / 4;
        cvt16_kernel<<<(n4 + 255) / 256, 256>>>(hidden, hid, n4);
        n4 = QKV_COLS * HIDDEN / 4;
        cvt16_kernel<<<(n4 + 255) / 256, 256>>>(qkv_w, w1, n4);
        n4 = HIDDEN * Q_SIZE / 4;
        cvt16_kernel<<<(n4 + 255) / 256, 256>>>(o_w, w2, n4);
        int nt = T * 64;
        rope_table_kernel<<<(nt + 255) / 256, 256>>>(pos, rope, T);
    }
    // 1) QKV projection
    {
        dim3 grid(QKV_COLS / XBN, T / XBM);
        gemm_f16<<<grid, 256, GEMM_SMEM>>>(hid, w1, qkv, T, QKV_COLS, HIDDEN);
    }
    // 2) Fused RMSNorm + RoPE (table-driven, fp32-only); transpose V
    {
        int warps = T * 24;
        int blocks = (warps + 7) / 8;
        normrope_split_kernel<<<blocks, 256>>>(qkv, q_nw, k_nw, rope, q, k, T);
        dim3 vg(T / 32, HEAD_DIM / 32, NUM_KV);
        vtrans_kernel<<<vg, dim3(32, 8)>>>(qkv, v, T);
    }
    // 3) Attention (unchanged champion)
    {
        dim3 grid(T / AQB, NUM_HEADS);
        attn_mma<<<grid, 128, ATT_SMEM>>>(q, k, v, at, T);
    }
    // 4) Output projection
    {
        dim3 grid(HIDDEN / XBN, T / XBM);
        gemm_f16<<<grid, 256, GEMM_SMEM>>>(at, w2, out, T, HIDDEN, HIDDEN);
    }
}

// round 17
// speedup vs baseline: 2.4207x; 1.0261x over previous
#include <cuda_runtime.h>
#include <cuda_bf16.h>
#include <cuda_fp16.h>
#include <math.h>
#include <float.h>
#include <cstdint>

// Problem constants
#define HIDDEN    2048
#define NUM_HEADS 16
#define NUM_KV    8
#define HEAD_DIM  128
#define Q_SIZE    (NUM_HEADS * HEAD_DIM)        // 2048
#define KV_SIZE   (NUM_KV * HEAD_DIM)           // 1024
#define QKV_COLS  (Q_SIZE + 2 * KV_SIZE)        // 4096
#define SCALE     0.08838834764831845f          // 128^-0.5
#define SCALE_L2E 0.12751985675839602f          // SCALE * log2(e)
#define RMS_EPS   1e-6f

#define MAX_T 4096

// Scratch (static device globals)
__device__ float g_qkv[(size_t)MAX_T * QKV_COLS];
__device__ __half g_hid[(size_t)MAX_T * HIDDEN];
__device__ __half g_w1[(size_t)QKV_COLS * HIDDEN];
__device__ __half g_w2[(size_t)HIDDEN * Q_SIZE];
__device__ __half g_at[(size_t)MAX_T * Q_SIZE];
__device__ __half g_q[(size_t)MAX_T * Q_SIZE];
__device__ __half g_k[(size_t)NUM_KV * MAX_T * HEAD_DIM];
__device__ __half g_v[(size_t)NUM_KV * HEAD_DIM * MAX_T];   // [kvh][d][t]
__device__ float2 g_rope[(size_t)MAX_T * 64];               // (t, j): cos, sin

// ===========================================================================
// Helpers
// ===========================================================================
__device__ __forceinline__ uint32_t smem_to_u32(const void* p) {
    uint32_t a;
    asm("{ .reg .u64 t; cvta.to.shared.u64 t, %1; cvt.u32.u64 %0, t; }"
        : "=r"(a) : "l"(p));
    return a;
}
__device__ __forceinline__ float ex2f(float x) {
    float r;
    asm("ex2.approx.f32 %0, %1;" : "=f"(r) : "f"(x));
    return r;
}
__device__ __forceinline__ uint32_t cvt_h2(float a, float b) {
    uint32_t r;
    asm("cvt.rn.f16x2.f32 %0, %1, %2;" : "=r"(r) : "f"(b), "f"(a));
    return r;
}

__device__ __forceinline__ void mma_f16(float* d, const uint32_t* a,
                                        uint32_t b0, uint32_t b1) {
    asm volatile(
        "mma.sync.aligned.m16n8k16.row.col.f32.f16.f16.f32 "
        "{%0,%1,%2,%3}, {%4,%5,%6,%7}, {%8,%9}, {%0,%1,%2,%3};"
        : "+f"(d[0]), "+f"(d[1]), "+f"(d[2]), "+f"(d[3])
        : "r"(a[0]), "r"(a[1]), "r"(a[2]), "r"(a[3]), "r"(b0), "r"(b1));
}

#define LDSM_X4(r0, r1, r2, r3, addr) \
    asm volatile("ldmatrix.sync.aligned.m8n8.x4.shared.b16 {%0,%1,%2,%3}, [%4];" \
        : "=r"(r0), "=r"(r1), "=r"(r2), "=r"(r3) : "r"(addr))

#define CP_ASYNC16(dst, src) \
    asm volatile("cp.async.cg.shared.global [%0], [%1], 16;" \
        :: "r"(dst), "l"(src))
#define CP_COMMIT() asm volatile("cp.async.commit_group;")
#define CP_WAIT(n)  asm volatile("cp.async.wait_group %0;" :: "n"(n))

// ---------------------------------------------------------------------------
// Pre/post kernels
// ---------------------------------------------------------------------------
__global__ __launch_bounds__(256) void cvt16_kernel(
    const float* __restrict__ src, __half* __restrict__ dst, int n4)
{
    int i = blockIdx.x * blockDim.x + threadIdx.x;
    if (i >= n4) return;
    float4 v = ((const float4*)src)[i];
    uint2 u;
    u.x = cvt_h2(v.x, v.y);
    u.y = cvt_h2(v.z, v.w);
    ((uint2*)dst)[i] = u;
}

// RoPE cos/sin table. fp64 only for freq (smem, 64 exps/block) and range
// reduction (exact); sincosf on reduced arg [-pi,pi] (err ~2e-7, negligible
// vs fp16 quantization).
__global__ __launch_bounds__(256) void rope_table_kernel(
    const int* __restrict__ positions, float2* __restrict__ tab, int T)
{
    __shared__ double sfreq[64];
    if (threadIdx.x < 64) {
        const double LOG_THETA = 13.815510557964274;   // ln(1e6)
        sfreq[threadIdx.x] =
            exp(-((double)(2 * threadIdx.x) / 128.0) * LOG_THETA);
    }
    __syncthreads();
    int i = blockIdx.x * blockDim.x + threadIdx.x;
    if (i >= T * 64) return;
    int t = i >> 6, j = i & 63;
    const double TWO_PI     = 6.283185307179586;
    const double INV_TWO_PI = 0.15915494309189535;
    double ang = (double)positions[t] * sfreq[j];
    double k = rint(ang * INV_TWO_PI);
    float red = (float)(ang - k * TWO_PI);
    float s, c;
    sincosf(red, &s, &c);
    tab[i] = make_float2(c, s);
}

// Fused RMSNorm + RoPE (pure fp32; angles from table). Q,K -> single fp16.
__global__ __launch_bounds__(256) void normrope_split_kernel(
    const float* __restrict__ qkv,
    const float* __restrict__ qw, const float* __restrict__ kw,
    const float2* __restrict__ rope,
    __half* __restrict__ q_g, __half* __restrict__ k_g, int T)
{
    const int warp = (blockIdx.x * blockDim.x + threadIdx.x) >> 5;
    const int lane = threadIdx.x & 31;
    if (warp >= T * 24) return;
    const int t = warp / 24;
    const int h = warp % 24;

    const float* x = qkv + (size_t)t * QKV_COLS + h * HEAD_DIM;
    const float* nw = (h < 16) ? qw : kw;

    float v0 = x[lane], v1 = x[lane + 32], v2 = x[lane + 64], v3 = x[lane + 96];
    float ss = v0 * v0 + v1 * v1 + v2 * v2 + v3 * v3;
    #pragma unroll
    for (int o = 16; o; o >>= 1) ss += __shfl_xor_sync(0xffffffffu, ss, o);
    const float rn = rsqrtf(ss * (1.0f / HEAD_DIM) + RMS_EPS);

    float n0 = v0 * rn * nw[lane];
    float n1 = v1 * rn * nw[lane + 32];
    float n2 = v2 * rn * nw[lane + 64];
    float n3 = v3 * rn * nw[lane + 96];

    float2 cs0 = rope[(size_t)t * 64 + lane];
    float2 cs1 = rope[(size_t)t * 64 + lane + 32];
    float c0 = cs0.x, s0 = cs0.y, c1 = cs1.x, s1 = cs1.y;

    float r0 = n0 * c0 - n2 * s0;
    float r2 = n2 * c0 + n0 * s0;
    float r1 = n1 * c1 - n3 * s1;
    float r3 = n3 * c1 + n1 * s1;

    __half* dst;
    size_t base;
    if (h < 16) {
        base = (size_t)t * Q_SIZE + h * HEAD_DIM;
        dst = q_g;
    } else {
        base = (size_t)(h - 16) * T * HEAD_DIM + (size_t)t * HEAD_DIM;
        dst = k_g;
    }
    dst[base + lane]      = __float2half_rn(r0);
    dst[base + lane + 32] = __float2half_rn(r1);
    dst[base + lane + 64] = __float2half_rn(r2);
    dst[base + lane + 96] = __float2half_rn(r3);
}

__global__ void vtrans_kernel(
    const float* __restrict__ qkv, __half* __restrict__ vh, int T)
{
    __shared__ float tile[32][33];
    const int kvh = blockIdx.z;
    const int d0 = blockIdx.y * 32;
    const int t0 = blockIdx.x * 32;
    for (int j = threadIdx.y; j < 32; j += 8) {
        tile[j][threadIdx.x] = qkv[(size_t)(t0 + j) * QKV_COLS + Q_SIZE + KV_SIZE
                                   + kvh * HEAD_DIM + d0 + threadIdx.x];
    }
    __syncthreads();
    for (int j = threadIdx.y; j < 32; j += 8) {
        float v = tile[threadIdx.x][j];
        size_t o = (size_t)kvh * HEAD_DIM * T + (size_t)(d0 + j) * T + t0 + threadIdx.x;
        vh[o] = __float2half_rn(v);
    }
}

// ---------------------------------------------------------------------------
// fp16 HMMA GEMM, single combo, BK=64, 3-stage cp.async pipeline,
// ONE sync per iteration. C[M,N] = A[M,K] * B[N,K]^T. 2 CTAs/SM.
// ---------------------------------------------------------------------------
#define XBM 128
#define XBN 128
#define XBK 64
#define XSTR 72                        // 64 + 8 pad
#define STAGE_E (XBM * XSTR)           // 9216 elems per buffer
#define NSTG 3
#define GEMM_SMEM (NSTG * 2 * STAGE_E * 2)   // 110592 bytes

__global__ __launch_bounds__(256, 2) void gemm_f16(
    const __half* __restrict__ A, const __half* __restrict__ B,
    float* __restrict__ C, int M, int N, int K)
{
    extern __shared__ __half smg[];
    const uint32_t smb = smem_to_u32(smg);

    const int tid  = threadIdx.x;
    const int lane = tid & 31;
    const int wid  = tid >> 5;
    const int gid  = lane >> 2;
    const int tq   = lane & 3;
    const int wm   = (wid & 3) * 32;
    const int wn   = (wid >> 2) * 64;

    const int arow  = lane & 15;
    const int acol8 = (lane >> 4) << 3;
    const int brow  = ((lane >> 4) << 3) + (lane & 7);
    const int bcol8 = ((lane >> 3) & 1) << 3;

    const int bm = blockIdx.y * XBM;
    const int bn = blockIdx.x * XBN;

    // 128 rows x 64 cols per buffer = 1024 uint4; 256 threads x 4 chunks
    #define G_ISSUE(stage, k0) do { \
        uint32_t sb0 = smb + (uint32_t)(stage) * 2 * STAGE_E * 2; \
        _Pragma("unroll") \
        for (int j = 0; j < 4; j++) { \
            int id = tid + j * 256; \
            int r = id >> 3, c = (id & 7) * 8; \
            size_t aoff = (size_t)(bm + r) * K + (k0) + c; \
            size_t boff = (size_t)(bn + r) * K + (k0) + c; \
            uint32_t doff = (uint32_t)(r * XSTR + c) * 2; \
            CP_ASYNC16(sb0 + doff, A + aoff); \
            CP_ASYNC16(sb0 + STAGE_E * 2 + doff, B + boff); \
        } \
    } while (0)

    float acc[2][8][4] = {};

    G_ISSUE(0, 0);
    CP_COMMIT();
    G_ISSUE(1, XBK);
    CP_COMMIT();

    int it = 0;
    for (int k0 = 0; k0 < K; k0 += XBK, it++) {
        CP_WAIT(1);        // group(it) complete (pending: it, it+1)
        __syncthreads();   // visibility + stage (it+2)%3 free for reuse

        int kn = k0 + 2 * XBK;
        if (kn < K) G_ISSUE((it + 2) % NSTG, kn);
        CP_COMMIT();       // unconditional: keeps group indexing aligned

        const int stage = it % NSTG;
        const uint32_t sA = smb + (uint32_t)stage * 2 * STAGE_E * 2;
        const uint32_t sB = sA + STAGE_E * 2;

        #pragma unroll
        for (int kk = 0; kk < XBK; kk += 16) {
            uint32_t a[2][4];
            #pragma unroll
            for (int mt = 0; mt < 2; mt++) {
                uint32_t aoff = (uint32_t)((wm + mt * 16 + arow) * XSTR + kk + acol8) * 2;
                LDSM_X4(a[mt][0], a[mt][1], a[mt][2], a[mt][3], sA + aoff);
            }
            #pragma unroll
            for (int p = 0; p < 4; p++) {
                uint32_t boff = (uint32_t)((wn + p * 16 + brow) * XSTR + kk + bcol8) * 2;
                uint32_t b0, b1, b2, b3;
                LDSM_X4(b0, b1, b2, b3, sB + boff);
                #pragma unroll
                for (int mt = 0; mt < 2; mt++) {
                    mma_f16(acc[mt][2 * p], a[mt], b0, b1);
                    mma_f16(acc[mt][2 * p + 1], a[mt], b2, b3);
                }
            }
        }
    }

    #pragma unroll
    for (int mt = 0; mt < 2; mt++) {
        int row = bm + wm + mt * 16 + gid;
        #pragma unroll
        for (int nt = 0; nt < 8; nt++) {
            int col = bn + wn + nt * 8 + tq * 2;
            *(float2*)&C[(size_t)row * N + col] =
                make_float2(acc[mt][nt][0], acc[mt][nt][1]);
            *(float2*)&C[(size_t)(row + 8) * N + col] =
                make_float2(acc[mt][nt][2], acc[mt][nt][3]);
        }
    }
}

// ---------------------------------------------------------------------------
// fp16 HMMA flash attention — UNCHANGED champion (q64 x kv64, 128 threads,
// 3 CTAs/SM, 1-combo QK/PV, persistent Q frags, double-buffered, 1 sync/iter)
// ---------------------------------------------------------------------------
#define AQB 64
#define AKB 64
#define SSTR 136
#define VSTR 72
#define KT_B (AKB * SSTR * 2)           // 17408 B
#define VT_B (HEAD_DIM * VSTR * 2)      // 18432 B
#define OFF_K(s)  ((uint32_t)(s) * KT_B)
#define OFF_V(s)  (2u * KT_B + (uint32_t)(s) * VT_B)
#define ATT_SMEM  (2 * KT_B + 2 * VT_B) // 71680 B

__global__ __launch_bounds__(128, 3) void attn_mma(
    const __half* __restrict__ q_g, const __half* __restrict__ k_g,
    const __half* __restrict__ v_g,
    __half* __restrict__ attn_out, int T)
{
    extern __shared__ char sm[];
    const uint32_t smb = smem_to_u32(sm);
    const int tid  = threadIdx.x;
    const int lane = tid & 31;
    const int wid  = tid >> 5;
    const int gid  = lane >> 2;
    const int tq   = lane & 3;

    const int qb   = (gridDim.x - 1) - blockIdx.x;
    const int head = blockIdx.y;
    const int kvh  = head >> 1;
    const int q0   = qb * AQB;
    const int wrow = wid * 16;
    const int iters = qb + 1;

    const int arow  = lane & 15;
    const int acol8 = (lane >> 4) << 3;
    const int brow  = ((lane >> 4) << 3) + (lane & 7);
    const int bcol8 = ((lane >> 3) & 1) << 3;

    const size_t kbase = (size_t)kvh * T * HEAD_DIM;
    const size_t vbase = (size_t)kvh * HEAD_DIM * T;

    #define ATT_PREFETCH(itn) do { \
        const int st_ = (itn) & 1; \
        const uint32_t kb_ = smb + OFF_K(st_); \
        const uint32_t vb_ = smb + OFF_V(st_); \
        const size_t ko_ = kbase + (size_t)(itn) * AKB * HEAD_DIM; \
        const size_t vo_ = vbase + (size_t)(itn) * AKB; \
        _Pragma("unroll") \
        for (int j = 0; j < 8; j++) { \
            int i = tid + j * 128; \
            int r_ = i >> 4, c_ = (i & 15) << 3; \
            uint32_t doff_ = (uint32_t)(r_ * SSTR + c_) * 2; \
            CP_ASYNC16(kb_ + doff_, k_g + ko_ + (size_t)r_ * HEAD_DIM + c_); \
            int d_ = i >> 3, vc_ = (i & 7) << 3; \
            uint32_t vdoff_ = (uint32_t)(d_ * VSTR + vc_) * 2; \
            CP_ASYNC16(vb_ + vdoff_, v_g + vo_ + (size_t)d_ * T + vc_); \
        } \
        CP_COMMIT(); \
    } while (0)

    for (int i = tid; i < 512; i += 128) {
        int r = i >> 3, c = (i & 7) << 4;
        uint32_t doff = (uint32_t)(r * SSTR + c) * 2;
        size_t o = (size_t)(q0 + r) * Q_SIZE + head * HEAD_DIM + c;
        *(uint4*)(sm + doff)      = *(const uint4*)&q_g[o];
        *(uint4*)(sm + doff + 16) = *(const uint4*)&q_g[o + 8];
    }
    __syncthreads();

    uint32_t qh[8][4];
    #pragma unroll
    for (int kt = 0; kt < 8; kt++) {
        uint32_t aoff = (uint32_t)((wrow + arow) * SSTR + kt * 16 + acol8) * 2;
        LDSM_X4(qh[kt][0], qh[kt][1], qh[kt][2], qh[kt][3], smb + aoff);
    }
    __syncthreads();

    ATT_PREFETCH(0);

    const int grow0 = q0 + wrow + gid;
    const int grow1 = grow0 + 8;

    float m0 = -1e30f, m1 = -1e30f, l0s = 0.0f, l1s = 0.0f;
    float o[16][4] = {};

    for (int it = 0; it < iters; it++) {
        const int k0 = it * AKB;
        const int st = it & 1;
        const uint32_t k_b = smb + OFF_K(st);
        const uint32_t v_b = smb + OFF_V(st);

        CP_WAIT(0);
        __syncthreads();

        if (it + 1 < iters) ATT_PREFETCH(it + 1);

        float s[8][4];
        #pragma unroll
        for (int nt = 0; nt < 8; nt++)
            #pragma unroll
            for (int c = 0; c < 4; c++) s[nt][c] = 0.0f;

        #pragma unroll
        for (int kt = 0; kt < 8; kt++) {
            #pragma unroll
            for (int p = 0; p < 4; p++) {
                uint32_t boff = (uint32_t)((p * 16 + brow) * SSTR + kt * 16 + bcol8) * 2;
                uint32_t b0, b1, b2, b3;
                LDSM_X4(b0, b1, b2, b3, k_b + boff);
                mma_f16(s[2 * p], qh[kt], b0, b1);
                mma_f16(s[2 * p + 1], qh[kt], b2, b3);
            }
        }

        const bool diag = (it == qb);
        float mx0 = m0, mx1 = m1;
        #pragma unroll
        for (int nt = 0; nt < 8; nt++) {
            int colb = k0 + nt * 8 + tq * 2;
            #pragma unroll
            for (int c = 0; c < 2; c++) {
                float v0 = s[nt][c] * SCALE_L2E;
                float v1 = s[nt][c + 2] * SCALE_L2E;
                if (diag && (colb + c > grow0)) v0 = -1e30f;
                if (diag && (colb + c > grow1)) v1 = -1e30f;
                s[nt][c] = v0; s[nt][c + 2] = v1;
                mx0 = fmaxf(mx0, v0); mx1 = fmaxf(mx1, v1);
            }
        }
        mx0 = fmaxf(mx0, __shfl_xor_sync(0xffffffffu, mx0, 1));
        mx0 = fmaxf(mx0, __shfl_xor_sync(0xffffffffu, mx0, 2));
        mx1 = fmaxf(mx1, __shfl_xor_sync(0xffffffffu, mx1, 1));
        mx1 = fmaxf(mx1, __shfl_xor_sync(0xffffffffu, mx1, 2));

        const float a0 = ex2f(m0 - mx0);
        const float a1 = ex2f(m1 - mx1);
        m0 = mx0; m1 = mx1;

        float sum0 = 0.0f, sum1 = 0.0f;
        #pragma unroll
        for (int nt = 0; nt < 8; nt++) {
            #pragma unroll
            for (int c = 0; c < 2; c++) {
                float p0 = ex2f(s[nt][c] - m0);
                float p1 = ex2f(s[nt][c + 2] - m1);
                s[nt][c] = p0; s[nt][c + 2] = p1;
                sum0 += p0; sum1 += p1;
            }
        }
        sum0 += __shfl_xor_sync(0xffffffffu, sum0, 1);
        sum0 += __shfl_xor_sync(0xffffffffu, sum0, 2);
        sum1 += __shfl_xor_sync(0xffffffffu, sum1, 1);
        sum1 += __shfl_xor_sync(0xffffffffu, sum1, 2);
        l0s = l0s * a0 + sum0;
        l1s = l1s * a1 + sum1;

        #pragma unroll
        for (int nt = 0; nt < 16; nt++) {
            o[nt][0] *= a0; o[nt][1] *= a0;
            o[nt][2] *= a1; o[nt][3] *= a1;
        }

        #pragma unroll
        for (int kt = 0; kt < 4; kt++) {
            uint32_t ph[4];
            ph[0] = cvt_h2(s[2 * kt][0], s[2 * kt][1]);
            ph[1] = cvt_h2(s[2 * kt][2], s[2 * kt][3]);
            ph[2] = cvt_h2(s[2 * kt + 1][0], s[2 * kt + 1][1]);
            ph[3] = cvt_h2(s[2 * kt + 1][2], s[2 * kt + 1][3]);
            #pragma unroll
            for (int p = 0; p < 8; p++) {
                uint32_t boff = (uint32_t)((p * 16 + brow) * VSTR + kt * 16 + bcol8) * 2;
                uint32_t v0r, v1r, v2r, v3r;
                LDSM_X4(v0r, v1r, v2r, v3r, v_b + boff);
                mma_f16(o[2 * p], ph, v0r, v1r);
                mma_f16(o[2 * p + 1], ph, v2r, v3r);
            }
        }
    }

    const float inv0 = 1.0f / l0s;
    const float inv1 = 1.0f / l1s;
    #pragma unroll
    for (int nt = 0; nt < 16; nt++) {
        int dcol = head * HEAD_DIM + nt * 8 + tq * 2;
        *(uint32_t*)&attn_out[(size_t)grow0 * Q_SIZE + dcol] =
            cvt_h2(o[nt][0] * inv0, o[nt][1] * inv0);
        *(uint32_t*)&attn_out[(size_t)grow1 * Q_SIZE + dcol] =
            cvt_h2(o[nt][2] * inv1, o[nt][3] * inv1);
    }
}

// ---------------------------------------------------------------------------
// Launch
// ---------------------------------------------------------------------------
extern "C" void kernel_launch(void* const* d_in, const int* in_sizes, int n_in,
                              void* d_out, int out_size)
{
    const float* hidden = (const float*)d_in[0];
    const float* qkv_w  = (const float*)d_in[1];
    const float* q_nw   = (const float*)d_in[2];
    const float* k_nw   = (const float*)d_in[3];
    const float* o_w    = (const float*)d_in[4];
    const int*   pos    = (const int*)d_in[5];
    float* out = (float*)d_out;

    const int T = in_sizes[0] / HIDDEN;

    float* qkv;  cudaGetSymbolAddress((void**)&qkv,  g_qkv);
    __half *hid, *w1, *w2, *at, *q, *k, *v;
    float2* rope;
    cudaGetSymbolAddress((void**)&hid,  g_hid);
    cudaGetSymbolAddress((void**)&w1,   g_w1);
    cudaGetSymbolAddress((void**)&w2,   g_w2);
    cudaGetSymbolAddress((void**)&at,   g_at);
    cudaGetSymbolAddress((void**)&q,    g_q);
    cudaGetSymbolAddress((void**)&k,    g_k);
    cudaGetSymbolAddress((void**)&v,    g_v);
    cudaGetSymbolAddress((void**)&rope, g_rope);

    cudaFuncSetAttribute(attn_mma, cudaFuncAttributeMaxDynamicSharedMemorySize,
                         ATT_SMEM);
    cudaFuncSetAttribute(gemm_f16, cudaFuncAttributeMaxDynamicSharedMemorySize,
                         GEMM_SMEM);

    // 0) Convert inputs to fp16 + build RoPE table
    {
        int n4 = T * HIDDEN / 4;
        cvt16_kernel<<<(n4 + 255) / 256, 256>>>(hidden, hid, n4);
        n4 = QKV_COLS * HIDDEN / 4;
        cvt16_kernel<<<(n4 + 255) / 256, 256>>>(qkv_w, w1, n4);
        n4 = HIDDEN * Q_SIZE / 4;
        cvt16_kernel<<<(n4 + 255) / 256, 256>>>(o_w, w2, n4);
        int nt = T * 64;
        rope_table_kernel<<<(nt + 255) / 256, 256>>>(pos, rope, T);
    }
    // 1) QKV projection (3-stage pipeline)
    {
        dim3 grid(QKV_COLS / XBN, T / XBM);
        gemm_f16<<<grid, 256, GEMM_SMEM>>>(hid, w1, qkv, T, QKV_COLS, HIDDEN);
    }
    // 2) Fused RMSNorm + RoPE (table-driven); transpose V
    {
        int warps = T * 24;
        int blocks = (warps + 7) / 8;
        normrope_split_kernel<<<blocks, 256>>>(qkv, q_nw, k_nw, rope, q, k, T);
        dim3 vg(T / 32, HEAD_DIM / 32, NUM_KV);
        vtrans_kernel<<<vg, dim3(32, 8)>>>(qkv, v, T);
    }
    // 3) Attention (unchanged champion)
    {
        dim3 grid(T / AQB, NUM_HEADS);
        attn_mma<<<grid, 128, ATT_SMEM>>>(q, k, v, at, T);
    }
    // 4) Output projection (3-stage pipeline)
    {
        dim3 grid(HIDDEN / XBN, T / XBM);
        gemm_f16<<<grid, 256, GEMM_SMEM>>>(at, w2, out, T, HIDDEN, HIDDEN);
    }
}